// round 9
// baseline (speedup 1.0000x reference)
#include <cuda_runtime.h>
#include <cuda_bf16.h>
#include <cstdint>

#define NNODES 20000
#define NEDGES 640000
#define DINF   92
#define DPAD   128
#define CF     128
#define NCF    (NNODES*CF)

// ---------------- scratch (device globals; no allocation) ----------------
__device__ __align__(16) float g_X[NCF];
__device__ __align__(16) float g_T[NCF];
__device__ __align__(16) float g_Hb[NCF];
__device__ __align__(16) float g_HHb[NNODES*256];
__device__ __align__(16) float g_AGG[NNODES*256];
__device__ __align__(16) float g_ZOUT[NCF];
__device__ __align__(16) float g_NF[NNODES*DPAD];
__device__ __align__(16) uint32_t g_BHI[98304];   // packed bf16-pair weight images
__device__ __align__(16) uint32_t g_BLO[98304];
__device__ __align__(16) float g_AS[NNODES*2];
__device__ __align__(16) float g_AD[NNODES*2];
__device__ __align__(16) float g_S1[CF];
__device__ __align__(16) float g_S2[CF];
__device__ __align__(16) float g_cs[CF];
__device__ __align__(16) float g_cb[CF];
__device__ int   g_cnt[NNODES];
__device__ int   g_rowptr[NNODES+1];
__device__ int   g_cursor[NNODES];
__device__ int   g_csrc[NEDGES];
__device__ int   g_bsum[32];
__device__ int   g_is64;

// ---------------- bf16 hi/lo split + pack ----------------
__device__ __forceinline__ void split_pack(float e0, float e1,
                                           uint32_t& hp, uint32_t& lp) {
    unsigned short h0 = __bfloat16_as_ushort(__float2bfloat16_rn(e0));
    unsigned short h1 = __bfloat16_as_ushort(__float2bfloat16_rn(e1));
    float f0 = __uint_as_float((uint32_t)h0 << 16);
    float f1 = __uint_as_float((uint32_t)h1 << 16);
    unsigned short l0 = __bfloat16_as_ushort(__float2bfloat16_rn(e0 - f0));
    unsigned short l1 = __bfloat16_as_ushort(__float2bfloat16_rn(e1 - f1));
    hp = (uint32_t)h0 | ((uint32_t)h1 << 16);
    lp = (uint32_t)l0 | ((uint32_t)l1 << 16);
}

__device__ __forceinline__ void mma16816(float& d0, float& d1, float& d2, float& d3,
                                         uint32_t a0, uint32_t a1, uint32_t a2, uint32_t a3,
                                         uint32_t b0, uint32_t b1) {
    asm volatile(
        "mma.sync.aligned.m16n8k16.row.col.f32.bf16.bf16.f32 "
        "{%0,%1,%2,%3}, {%4,%5,%6,%7}, {%8,%9}, {%0,%1,%2,%3};"
        : "+f"(d0), "+f"(d1), "+f"(d2), "+f"(d3)
        : "r"(a0), "r"(a1), "r"(a2), "r"(a3), "r"(b0), "r"(b1));
}

__device__ __forceinline__ int edge_src(const void* p, int e) {
    return g_is64 ? (int)((const long long*)p)[e] : ((const int*)p)[e];
}
__device__ __forceinline__ int edge_dst(const void* p, int e) {
    return g_is64 ? (int)((const long long*)p)[NEDGES + e] : ((const int*)p)[NEDGES + e];
}

// ---------------- init: zero counters + stats, detect edge dtype ----------------
__global__ void init_kernel(const void* idx) {
    int i = blockIdx.x * blockDim.x + threadIdx.x;
    if (i < NNODES) g_cnt[i] = 0;
    if (i < CF) { g_S1[i] = 0.f; g_S2[i] = 0.f; }
    if (blockIdx.x == gridDim.x - 1) {
        const int* w = (const int*)idx;
        __shared__ int nz;
        if (threadIdx.x == 0) nz = 0;
        __syncthreads();
        for (int t = threadIdx.x; t < 4096; t += blockDim.x) {
            long long pos = 2LL * t * (NEDGES / 4096) + 1;
            if (pos < 2LL * NEDGES && w[pos] != 0) atomicOr(&nz, 1);
        }
        __syncthreads();
        if (threadIdx.x == 0) g_is64 = (nz == 0) ? 1 : 0;
    }
}

// ---------------- CSR build ----------------
__global__ void hist_kernel(const void* eidx) {
    int e = blockIdx.x * blockDim.x + threadIdx.x;
    if (e < NEDGES) atomicAdd(&g_cnt[edge_dst(eidx, e)], 1);
}
__global__ void scan1_kernel() {
    __shared__ int ws[32];
    int b = blockIdx.x, tid = threadIdx.x, lane = tid & 31, wid = tid >> 5;
    int i = b * 1024 + tid;
    int v = (i < NNODES) ? g_cnt[i] : 0;
    int x = v;
    #pragma unroll
    for (int o = 1; o < 32; o <<= 1) {
        int y = __shfl_up_sync(0xffffffffu, x, o);
        if (lane >= o) x += y;
    }
    if (lane == 31) ws[wid] = x;
    __syncthreads();
    if (wid == 0) {
        int s = ws[lane];
        #pragma unroll
        for (int o = 1; o < 32; o <<= 1) {
            int y = __shfl_up_sync(0xffffffffu, s, o);
            if (lane >= o) s += y;
        }
        ws[lane] = s;
    }
    __syncthreads();
    int incl = x + (wid > 0 ? ws[wid - 1] : 0);
    if (i < NNODES) g_rowptr[i] = incl - v;
    if (tid == 1023) g_bsum[b] = incl;
}
__global__ void scan3_kernel() {
    int b = blockIdx.x;
    int off = 0;
    #pragma unroll
    for (int j = 0; j < 20; j++) off += (j < b) ? g_bsum[j] : 0;
    int i = b * 1024 + threadIdx.x;
    if (i < NNODES) {
        int r = g_rowptr[i] + off;
        g_rowptr[i] = r;
        g_cursor[i] = r;
    }
    if (b == 0 && threadIdx.x == 0) {
        int t = 0;
        #pragma unroll
        for (int j = 0; j < 20; j++) t += g_bsum[j];
        g_rowptr[NNODES] = t;
    }
}
__global__ void scatter_kernel(const void* eidx) {
    int e = blockIdx.x * blockDim.x + threadIdx.x;
    if (e < NEDGES) {
        int d = edge_dst(eidx, e);
        int s = edge_src(eidx, e);
        int p = atomicAdd(&g_cursor[d], 1);
        g_csrc[p] = s;
    }
}

// ---------------- pad node features 92 -> 128 ----------------
__global__ void pad_nf_kernel(const float* __restrict__ nf) {
    int i = blockIdx.x * blockDim.x + threadIdx.x;
    if (i < NNODES * DPAD) {
        int n = i >> 7, c = i & 127;
        g_NF[i] = (c < DINF) ? nf[n * DINF + c] : 0.f;
    }
}

// ---------------- pack ALL weights in one launch ----------------
__global__ void packall_kernel(const float* __restrict__ We, const float* __restrict__ W1,
                               const float* __restrict__ W2, const float* __restrict__ Wm,
                               const float* __restrict__ Wv, const float* __restrict__ Wg,
                               const float* __restrict__ Wd) {
    int idx = blockIdx.x * blockDim.x + threadIdx.x;
    const float* W; int Kreal, Kpad, N; uint32_t base; int local;
    if      (idx <  8192) { W = We; Kreal = DINF; Kpad = 128; N = 128; base = 0;     local = idx; }
    else if (idx < 16384) { W = W1; Kreal = 128;  Kpad = 128; N = 128; base = 8192;  local = idx - 8192; }
    else if (idx < 24576) { W = W2; Kreal = 128;  Kpad = 128; N = 128; base = 16384; local = idx - 16384; }
    else if (idx < 32768) { W = Wm; Kreal = 128;  Kpad = 128; N = 128; base = 24576; local = idx - 24576; }
    else if (idx < 40960) { W = Wv; Kreal = 128;  Kpad = 128; N = 128; base = 32768; local = idx - 32768; }
    else if (idx < 57344) { W = Wg; Kreal = 128;  Kpad = 128; N = 256; base = 40960; local = idx - 40960; }
    else if (idx < 73728) { W = Wd; Kreal = 256;  Kpad = 256; N = 128; base = 57344; local = idx - 57344; }
    else return;
    int pairs = Kpad >> 1;
    int n = local / pairs, kp = local - n * pairs;
    int nb = n >> 7, nr = n & 127;
    int k0 = 2 * kp;
    float v0 = (k0     < Kreal) ? W[k0 * N + n]       : 0.f;
    float v1 = (k0 + 1 < Kreal) ? W[(k0 + 1) * N + n] : 0.f;
    uint32_t hp, lp;
    split_pack(v0, v1, hp, lp);
    uint32_t off = base + (uint32_t)nb * 128u * pairs + (uint32_t)nr * pairs + kp;
    g_BHI[off] = hp;
    g_BLO[off] = lp;
}

// ================= bf16 3-product mma.sync GEMM (reg-prefetch pipelined) ========
// Out rows local to nb: out addr = Out + nb*nbstride + row*ldo + local_col.
// bias for nb=0; bias2 (if set) for nb=1. Kc = K/32.
__global__ void __launch_bounds__(256, 2)
mm_gemm(const float* __restrict__ A, int lda, int Kc, int M,
        uint32_t bbase,
        const float* __restrict__ bias, const float* __restrict__ bias2,
        float* __restrict__ Out, int ldo, int nbstride,
        const float* __restrict__ affs, const float* __restrict__ affb,
        int do_stats,
        const float* __restrict__ atts, const float* __restrict__ attd)
{
    __shared__ uint32_t AHI[128 * 20], ALO[128 * 20];
    __shared__ uint32_t BHI[128 * 20], BLO[128 * 20];
    __shared__ float    RED1[128], RED2[128];

    const int tid = threadIdx.x, wid = tid >> 5, lane = tid & 31;
    const int g = lane >> 2, tc = lane & 3;
    const int wm = wid >> 2, wn = wid & 3;
    const int r0 = blockIdx.x * 128;
    const int nb = blockIdx.y;
    const int pairsK = Kc * 16;
    const uint32_t bimg = bbase + (uint32_t)nb * 128u * pairsK;

    // per-thread staging slots
    const int srow = tid >> 4, sp = tid & 15;      // A/B row + pair for 8 strided slots
    const int grow_s = r0 + srow;

    float2   apre[8];
    uint32_t bhp[8], blp[8];

    // prologue: load chunk 0 into regs
    {
        #pragma unroll
        for (int i = 0; i < 8; i++) {
            int row = srow + i * 16;
            int gr = r0 + row;
            float2 v = make_float2(0.f, 0.f);
            if (gr < M) v = *(const float2*)&A[(size_t)gr * lda + sp * 2];
            apre[i] = v;
        }
        #pragma unroll
        for (int i = 0; i < 8; i++) {
            int n = srow + i * 16;
            uint32_t src = bimg + (uint32_t)n * pairsK + sp;
            bhp[i] = g_BHI[src];
            blp[i] = g_BLO[src];
        }
    }

    float acc[4][4][4];
    #pragma unroll
    for (int mt = 0; mt < 4; mt++)
        #pragma unroll
        for (int nt = 0; nt < 4; nt++)
            #pragma unroll
            for (int q = 0; q < 4; q++) acc[mt][nt][q] = 0.f;

    for (int c = 0; c < Kc; c++) {
        __syncthreads();   // all warps done with previous chunk's MMA reads
        // ---- store regs -> smem (split A with optional affine+relu)
        {
            int k = c * 32 + sp * 2;
            #pragma unroll
            for (int i = 0; i < 8; i++) {
                int row = srow + i * 16;
                float2 v = apre[i];
                if (affs) {
                    v.x = fmaxf(affs[k    ] * v.x + affb[k    ], 0.f);
                    v.y = fmaxf(affs[k + 1] * v.y + affb[k + 1], 0.f);
                }
                uint32_t hp, lp;
                split_pack(v.x, v.y, hp, lp);
                AHI[row * 20 + sp] = hp;
                ALO[row * 20 + sp] = lp;
                BHI[row * 20 + sp] = bhp[i];
                BLO[row * 20 + sp] = blp[i];
            }
        }
        __syncthreads();
        // ---- prefetch next chunk gmem -> regs (flies during MMA below)
        if (c + 1 < Kc) {
            int kb = (c + 1) * 32 + sp * 2;
            #pragma unroll
            for (int i = 0; i < 8; i++) {
                int gr = grow_s + i * 16;
                float2 v = make_float2(0.f, 0.f);
                if (gr < M) v = *(const float2*)&A[(size_t)gr * lda + kb];
                apre[i] = v;
            }
            uint32_t sb = bimg + (c + 1) * 16 + sp;
            #pragma unroll
            for (int i = 0; i < 8; i++) {
                uint32_t src = sb + (uint32_t)(srow + i * 16) * pairsK;
                bhp[i] = g_BHI[src];
                blp[i] = g_BLO[src];
            }
        }

        // ---- 3 products x 2 k16-steps x 16 mma
        #pragma unroll
        for (int prod = 0; prod < 3; prod++) {
            const uint32_t* Ab = (prod == 2) ? ALO : AHI;
            const uint32_t* Bb = (prod == 1) ? BLO : BHI;
            #pragma unroll
            for (int ks = 0; ks < 2; ks++) {
                uint32_t af[4][4], bf[4][2];
                #pragma unroll
                for (int mt = 0; mt < 4; mt++) {
                    int rbase = (wm * 64 + mt * 16 + g) * 20 + ks * 8 + tc;
                    af[mt][0] = Ab[rbase];
                    af[mt][1] = Ab[rbase + 8 * 20];
                    af[mt][2] = Ab[rbase + 4];
                    af[mt][3] = Ab[rbase + 8 * 20 + 4];
                }
                #pragma unroll
                for (int nt = 0; nt < 4; nt++) {
                    int nbase = (wn * 32 + nt * 8 + g) * 20 + ks * 8 + tc;
                    bf[nt][0] = Bb[nbase];
                    bf[nt][1] = Bb[nbase + 4];
                }
                #pragma unroll
                for (int mt = 0; mt < 4; mt++)
                    #pragma unroll
                    for (int nt = 0; nt < 4; nt++)
                        mma16816(acc[mt][nt][0], acc[mt][nt][1],
                                 acc[mt][nt][2], acc[mt][nt][3],
                                 af[mt][0], af[mt][1], af[mt][2], af[mt][3],
                                 bf[nt][0], bf[nt][1]);
            }
        }
    }

    // ---- epilogue
    const float* bsel = (nb == 1 && bias2) ? bias2 : bias;
    float bc[4][2];
    #pragma unroll
    for (int nt = 0; nt < 4; nt++) {
        int cc = wn * 32 + nt * 8 + tc * 2;
        bc[nt][0] = bsel ? bsel[cc]     : 0.f;
        bc[nt][1] = bsel ? bsel[cc + 1] : 0.f;
    }

    float* outp = Out + (size_t)nb * nbstride;
    #pragma unroll
    for (int mt = 0; mt < 4; mt++) {
        int row0 = r0 + wm * 64 + mt * 16 + g;
        int row1 = row0 + 8;
        #pragma unroll
        for (int nt = 0; nt < 4; nt++) {
            int cc = wn * 32 + nt * 8 + tc * 2;
            if (row0 < M) {
                float2 o = make_float2(acc[mt][nt][0] + bc[nt][0],
                                       acc[mt][nt][1] + bc[nt][1]);
                *(float2*)&outp[(size_t)row0 * ldo + cc] = o;
            }
            if (row1 < M) {
                float2 o = make_float2(acc[mt][nt][2] + bc[nt][0],
                                       acc[mt][nt][3] + bc[nt][1]);
                *(float2*)&outp[(size_t)row1 * ldo + cc] = o;
            }
        }
    }

    if (do_stats) {
        if (tid < CF) { RED1[tid] = 0.f; RED2[tid] = 0.f; }
        __syncthreads();
        #pragma unroll
        for (int nt = 0; nt < 4; nt++) {
            int ccl = wn * 32 + nt * 8 + tc * 2;
            float s0 = 0.f, q0 = 0.f, s1 = 0.f, q1 = 0.f;
            #pragma unroll
            for (int mt = 0; mt < 4; mt++) {
                int row0 = r0 + wm * 64 + mt * 16 + g;
                if (row0 < M) {
                    float v0 = acc[mt][nt][0] + bc[nt][0];
                    float v1 = acc[mt][nt][1] + bc[nt][1];
                    s0 += v0; q0 += v0 * v0; s1 += v1; q1 += v1 * v1;
                }
                if (row0 + 8 < M) {
                    float v0 = acc[mt][nt][2] + bc[nt][0];
                    float v1 = acc[mt][nt][3] + bc[nt][1];
                    s0 += v0; q0 += v0 * v0; s1 += v1; q1 += v1 * v1;
                }
            }
            atomicAdd(&RED1[ccl], s0); atomicAdd(&RED2[ccl], q0);
            atomicAdd(&RED1[ccl + 1], s1); atomicAdd(&RED2[ccl + 1], q1);
        }
        __syncthreads();
        if (tid < CF) { atomicAdd(&g_S1[tid], RED1[tid]); atomicAdd(&g_S2[tid], RED2[tid]); }
    }

    if (atts) {
        if (tid < 128) { RED1[tid] = 0.f; RED2[tid] = 0.f; }
        __syncthreads();
        float avs[4][2], avd[4][2];
        #pragma unroll
        for (int nt = 0; nt < 4; nt++) {
            int cc = wn * 32 + nt * 8 + tc * 2;
            avs[nt][0] = atts[nb * CF + cc]; avs[nt][1] = atts[nb * CF + cc + 1];
            avd[nt][0] = attd[nb * CF + cc]; avd[nt][1] = attd[nb * CF + cc + 1];
        }
        #pragma unroll
        for (int mt = 0; mt < 4; mt++) {
            float ss0 = 0.f, sd0 = 0.f, ss1 = 0.f, sd1 = 0.f;
            #pragma unroll
            for (int nt = 0; nt < 4; nt++) {
                ss0 += acc[mt][nt][0] * avs[nt][0] + acc[mt][nt][1] * avs[nt][1];
                sd0 += acc[mt][nt][0] * avd[nt][0] + acc[mt][nt][1] * avd[nt][1];
                ss1 += acc[mt][nt][2] * avs[nt][0] + acc[mt][nt][3] * avs[nt][1];
                sd1 += acc[mt][nt][2] * avd[nt][0] + acc[mt][nt][3] * avd[nt][1];
            }
            int rl = wm * 64 + mt * 16 + g;
            atomicAdd(&RED1[rl], ss0);     atomicAdd(&RED2[rl], sd0);
            atomicAdd(&RED1[rl + 8], ss1); atomicAdd(&RED2[rl + 8], sd1);
        }
        __syncthreads();
        if (tid < 128 && r0 + tid < M) {
            g_AS[(r0 + tid) * 2 + nb] = RED1[tid];
            g_AD[(r0 + tid) * 2 + nb] = RED2[tid];
        }
    }
}

// ---------------- z = eps*exp(0.5*logvar)+mu ----------------
__global__ void z_kernel(const float* __restrict__ eps, float* __restrict__ out) {
    int i = blockIdx.x * blockDim.x + threadIdx.x;
    if (i < NCF) {
        float mu = out[2 * NCF + i];
        float lv = out[3 * NCF + i];
        out[i] = eps[i] * expf(0.5f * lv) + mu;
    }
}

// ---------------- BN finalize (self-resetting stats) ----------------
__global__ void bn_fin_kernel(const float* __restrict__ gam, const float* __restrict__ bet) {
    int c = threadIdx.x;
    if (c < CF) {
        float s1 = g_S1[c], s2 = g_S2[c];
        float mu  = s1 / (float)NNODES;
        float var = s2 / (float)NNODES - mu * mu;
        float a   = gam[c] * rsqrtf(var + 1e-5f);
        g_cs[c] = a;
        g_cb[c] = bet[c] - mu * a;
        g_S1[c] = 0.f;
        g_S2[c] = 0.f;
    }
}

// ---------------- GIN aggregation (optional fused affine+relu on gathered rows) ----
__global__ void gin_agg_kernel(const float* __restrict__ src,
                               const float* __restrict__ cs,
                               const float* __restrict__ cb) {
    int warp = (blockIdx.x * blockDim.x + threadIdx.x) >> 5;
    int lane = threadIdx.x & 31;
    if (warp >= NNODES) return;
    int n = warp;
    const bool aff = (cs != nullptr);
    float4 sc = make_float4(1.f, 1.f, 1.f, 1.f), bb = make_float4(0.f, 0.f, 0.f, 0.f);
    if (aff) {
        sc = *(const float4*)&cs[lane * 4];
        bb = *(const float4*)&cb[lane * 4];
    }
    float4 acc = *(const float4*)&src[n * CF + lane * 4];
    if (aff) {
        acc.x = fmaxf(sc.x * acc.x + bb.x, 0.f);
        acc.y = fmaxf(sc.y * acc.y + bb.y, 0.f);
        acc.z = fmaxf(sc.z * acc.z + bb.z, 0.f);
        acc.w = fmaxf(sc.w * acc.w + bb.w, 0.f);
    }
    int beg = g_rowptr[n], end = g_rowptr[n + 1];
    int i = beg;
    for (; i + 1 < end; i += 2) {
        int s0 = g_csrc[i], s1v = g_csrc[i + 1];
        float4 v0 = *(const float4*)&src[s0 * CF + lane * 4];
        float4 v1 = *(const float4*)&src[s1v * CF + lane * 4];
        if (aff) {
            v0.x = fmaxf(sc.x * v0.x + bb.x, 0.f); v0.y = fmaxf(sc.y * v0.y + bb.y, 0.f);
            v0.z = fmaxf(sc.z * v0.z + bb.z, 0.f); v0.w = fmaxf(sc.w * v0.w + bb.w, 0.f);
            v1.x = fmaxf(sc.x * v1.x + bb.x, 0.f); v1.y = fmaxf(sc.y * v1.y + bb.y, 0.f);
            v1.z = fmaxf(sc.z * v1.z + bb.z, 0.f); v1.w = fmaxf(sc.w * v1.w + bb.w, 0.f);
        }
        acc.x += v0.x + v1.x; acc.y += v0.y + v1.y;
        acc.z += v0.z + v1.z; acc.w += v0.w + v1.w;
    }
    if (i < end) {
        int s0 = g_csrc[i];
        float4 v0 = *(const float4*)&src[s0 * CF + lane * 4];
        if (aff) {
            v0.x = fmaxf(sc.x * v0.x + bb.x, 0.f); v0.y = fmaxf(sc.y * v0.y + bb.y, 0.f);
            v0.z = fmaxf(sc.z * v0.z + bb.z, 0.f); v0.w = fmaxf(sc.w * v0.w + bb.w, 0.f);
        }
        acc.x += v0.x; acc.y += v0.y; acc.z += v0.z; acc.w += v0.w;
    }
    *(float4*)&g_Hb[n * CF + lane * 4] = acc;
}

__device__ __forceinline__ float lrelu(float x) { return x > 0.f ? x : 0.2f * x; }

// ---------------- GAT aggregation: ONE warp per node, BOTH heads ----------------
__global__ void gat_agg_kernel(const float* __restrict__ b_gat) {
    int warp = (blockIdx.x * blockDim.x + threadIdx.x) >> 5;
    int lane = threadIdx.x & 31;
    if (warp >= NNODES) return;
    int n = warp;
    float2 ad  = *(const float2*)&g_AD[n * 2];
    float2 asn = *(const float2*)&g_AS[n * 2];
    float ls0 = lrelu(asn.x + ad.x);
    float ls1 = lrelu(asn.y + ad.y);
    int beg = g_rowptr[n], end = g_rowptr[n + 1];

    float m0 = ls0, m1 = ls1;
    for (int i = beg + lane; i < end; i += 32) {
        int s = g_csrc[i];
        float2 a = *(const float2*)&g_AS[s * 2];
        m0 = fmaxf(m0, lrelu(a.x + ad.x));
        m1 = fmaxf(m1, lrelu(a.y + ad.y));
    }
    #pragma unroll
    for (int o = 16; o >= 1; o >>= 1) {
        m0 = fmaxf(m0, __shfl_xor_sync(0xffffffffu, m0, o));
        m1 = fmaxf(m1, __shfl_xor_sync(0xffffffffu, m1, o));
    }

    float w0 = expf(ls0 - m0), w1 = expf(ls1 - m1);
    float s0 = w0, s1 = w1;
    const float* hn = &g_HHb[n * 256];
    float4 h0 = *(const float4*)&hn[lane * 4];
    float4 h1 = *(const float4*)&hn[128 + lane * 4];
    float4 acc0 = make_float4(w0 * h0.x, w0 * h0.y, w0 * h0.z, w0 * h0.w);
    float4 acc1 = make_float4(w1 * h1.x, w1 * h1.y, w1 * h1.z, w1 * h1.w);
    int i = beg;
    for (; i + 1 < end; i += 2) {
        int sa = g_csrc[i], sb = g_csrc[i + 1];
        float2 aa = *(const float2*)&g_AS[sa * 2];
        float2 ab = *(const float2*)&g_AS[sb * 2];
        float ea0 = expf(lrelu(aa.x + ad.x) - m0), ea1 = expf(lrelu(aa.y + ad.y) - m1);
        float eb0 = expf(lrelu(ab.x + ad.x) - m0), eb1 = expf(lrelu(ab.y + ad.y) - m1);
        s0 += ea0 + eb0; s1 += ea1 + eb1;
        const float* ha = &g_HHb[sa * 256];
        const float* hb = &g_HHb[sb * 256];
        float4 va0 = *(const float4*)&ha[lane * 4];
        float4 va1 = *(const float4*)&ha[128 + lane * 4];
        float4 vb0 = *(const float4*)&hb[lane * 4];
        float4 vb1 = *(const float4*)&hb[128 + lane * 4];
        acc0.x += ea0 * va0.x + eb0 * vb0.x; acc0.y += ea0 * va0.y + eb0 * vb0.y;
        acc0.z += ea0 * va0.z + eb0 * vb0.z; acc0.w += ea0 * va0.w + eb0 * vb0.w;
        acc1.x += ea1 * va1.x + eb1 * vb1.x; acc1.y += ea1 * va1.y + eb1 * vb1.y;
        acc1.z += ea1 * va1.z + eb1 * vb1.z; acc1.w += ea1 * va1.w + eb1 * vb1.w;
    }
    if (i < end) {
        int sa = g_csrc[i];
        float2 aa = *(const float2*)&g_AS[sa * 2];
        float ea0 = expf(lrelu(aa.x + ad.x) - m0), ea1 = expf(lrelu(aa.y + ad.y) - m1);
        s0 += ea0; s1 += ea1;
        const float* ha = &g_HHb[sa * 256];
        float4 va0 = *(const float4*)&ha[lane * 4];
        float4 va1 = *(const float4*)&ha[128 + lane * 4];
        acc0.x += ea0 * va0.x; acc0.y += ea0 * va0.y;
        acc0.z += ea0 * va0.z; acc0.w += ea0 * va0.w;
        acc1.x += ea1 * va1.x; acc1.y += ea1 * va1.y;
        acc1.z += ea1 * va1.z; acc1.w += ea1 * va1.w;
    }
    float i0 = 1.f / s0, i1 = 1.f / s1;
    float4 bg0 = *(const float4*)&b_gat[lane * 4];
    float4 bg1 = *(const float4*)&b_gat[128 + lane * 4];
    float4 o0 = make_float4(acc0.x * i0 + bg0.x, acc0.y * i0 + bg0.y,
                            acc0.z * i0 + bg0.z, acc0.w * i0 + bg0.w);
    float4 o1 = make_float4(acc1.x * i1 + bg1.x, acc1.y * i1 + bg1.y,
                            acc1.z * i1 + bg1.z, acc1.w * i1 + bg1.w);
    *(float4*)&g_AGG[n * 256 + lane * 4]       = o0;
    *(float4*)&g_AGG[n * 256 + 128 + lane * 4] = o1;
}

// ---------------- host orchestration ----------------
extern "C" void kernel_launch(void* const* d_in, const int* in_sizes, int n_in,
                              void* d_out, int out_size) {
    const float* nf     = (const float*)d_in[0];
    const void*  eidx   =               d_in[1];
    const float* eps    = (const float*)d_in[2];
    const float* W_emb  = (const float*)d_in[3];
    const float* b_emb  = (const float*)d_in[4];
    const float* g_embp = (const float*)d_in[5];
    const float* be_emb = (const float*)d_in[6];
    const float* W1     = (const float*)d_in[7];
    const float* b1     = (const float*)d_in[8];
    const float* g1     = (const float*)d_in[9];
    const float* be1    = (const float*)d_in[10];
    const float* W2     = (const float*)d_in[11];
    const float* b2     = (const float*)d_in[12];
    const float* W_mu   = (const float*)d_in[13];
    const float* b_mu   = (const float*)d_in[14];
    const float* W_var  = (const float*)d_in[15];
    const float* b_var  = (const float*)d_in[16];
    const float* W_gat  = (const float*)d_in[17];
    const float* att_s  = (const float*)d_in[18];
    const float* att_d  = (const float*)d_in[19];
    const float* b_gat  = (const float*)d_in[20];
    const float* W_dec  = (const float*)d_in[21];
    const float* b_dec  = (const float*)d_in[22];
    float* out = (float*)d_out;

    float *X, *T, *Hb, *HHp, *AGG, *ZOUT, *CS, *CB, *NF;
    cudaGetSymbolAddress((void**)&X,    g_X);
    cudaGetSymbolAddress((void**)&T,    g_T);
    cudaGetSymbolAddress((void**)&Hb,   g_Hb);
    cudaGetSymbolAddress((void**)&HHp,  g_HHb);
    cudaGetSymbolAddress((void**)&AGG,  g_AGG);
    cudaGetSymbolAddress((void**)&ZOUT, g_ZOUT);
    cudaGetSymbolAddress((void**)&CS,   g_cs);
    cudaGetSymbolAddress((void**)&CB,   g_cb);
    cudaGetSymbolAddress((void**)&NF,   g_NF);

    const int GX = (NNODES + 127) / 128;   // 157
    dim3 grid1(GX, 1), grid2(GX, 2);
    const int EB = (NEDGES + 255) / 256;
    const int NB = (NNODES + 255) / 256;
    const int WARP_N = (NNODES * 32 + 255) / 256;
    const int PB  = (NNODES * DPAD + 255) / 256;
    const int ELB = (NCF + 255) / 256;

    const uint32_t O_EMB = 0, O_W1 = 8192, O_W2 = 16384, O_MU = 24576,
                   O_GAT = 40960, O_DEC = 57344;   // O_VAR = O_MU + 8192 (nb=1)

    // launches 1-5 (profiler skips these), 6th = mm_gemm (profiled by ncu -s 5 -c 1)
    packall_kernel<<<(73728 + 255) / 256, 256>>>(W_emb, W1, W2, W_mu, W_var, W_gat, W_dec);
    pad_nf_kernel<<<PB, 256>>>(nf);
    init_kernel<<<NB, 256>>>(eidx);
    hist_kernel<<<EB, 256>>>(eidx);
    scan1_kernel<<<20, 1024>>>();
    // 6th: atom embedding GEMM
    mm_gemm<<<grid1, 256>>>(NF, DPAD, 4, NNODES, O_EMB, b_emb, nullptr, T, CF, 0,
                            nullptr, nullptr, 1, nullptr, nullptr);
    scan3_kernel<<<20, 1024>>>();
    scatter_kernel<<<EB, 256>>>(eidx);
    bn_fin_kernel<<<1, 128>>>(g_embp, be_emb);

    // GIN layer 0 (agg applies emb-BN affine+relu to gathered rows of T)
    gin_agg_kernel<<<WARP_N, 256>>>(T, CS, CB);
    mm_gemm<<<grid1, 256>>>(Hb, CF, 4, NNODES, O_W1, b1, nullptr, T, CF, 0,
                            nullptr, nullptr, 1, nullptr, nullptr);
    bn_fin_kernel<<<1, 128>>>(g1, be1);
    mm_gemm<<<grid1, 256>>>(T, CF, 4, NNODES, O_W2, b2, nullptr, X, CF, 0,
                            CS, CB, 0, nullptr, nullptr);

    // GIN layer 1 (raw x)
    gin_agg_kernel<<<WARP_N, 256>>>(X, nullptr, nullptr);
    mm_gemm<<<grid1, 256>>>(Hb, CF, 4, NNODES, O_W1, b1, nullptr, T, CF, 0,
                            nullptr, nullptr, 1, nullptr, nullptr);
    bn_fin_kernel<<<1, 128>>>(g1, be1);
    mm_gemm<<<grid1, 256>>>(T, CF, 4, NNODES, O_W2, b2, nullptr, X, CF, 0,
                            CS, CB, 0, nullptr, nullptr);

    // VAE heads merged: nb=0 -> mu (out+2NCF), nb=1 -> logvar (out+3NCF)
    mm_gemm<<<grid2, 256>>>(X, CF, 4, NNODES, O_MU, b_mu, b_var,
                            out + 2 * NCF, CF, NCF,
                            nullptr, nullptr, 0, nullptr, nullptr);
    z_kernel<<<ELB, 256>>>(eps, out);

    // GAT decoder x2 (shared weights)
    for (int l = 0; l < 2; l++) {
        const float* zcur = (l == 0) ? out : ZOUT;
        float* zdst       = (l == 0) ? ZOUT : out + NCF;
        mm_gemm<<<grid2, 256>>>(zcur, CF, 4, NNODES, O_GAT, nullptr, nullptr,
                                HHp, 256, 128,
                                nullptr, nullptr, 0, att_s, att_d);
        gat_agg_kernel<<<WARP_N, 256>>>(b_gat);
        mm_gemm<<<grid1, 256>>>(AGG, 256, 8, NNODES, O_DEC, b_dec, nullptr, zdst, CF, 0,
                                nullptr, nullptr, 0, nullptr, nullptr);
    }
    (void)in_sizes; (void)n_in; (void)out_size;
}

// round 10
// speedup vs baseline: 1.1340x; 1.1340x over previous
#include <cuda_runtime.h>
#include <cuda_bf16.h>
#include <cstdint>

#define NNODES 20000
#define NEDGES 640000
#define DINF   92
#define DPAD   128
#define CF     128
#define NCF    (NNODES*CF)

// ---------------- scratch (device globals; no allocation) ----------------
__device__ __align__(16) float g_X[NCF];
__device__ __align__(16) float g_T[NCF];
__device__ __align__(16) float g_Hb[NCF];
__device__ __align__(16) float g_HHb[NNODES*128];   // bf16x2: [n][128 pairs] = 256 ch
__device__ __align__(16) float g_AGG[NNODES*256];
__device__ __align__(16) float g_ZOUT[NCF];
__device__ __align__(16) float g_NF[NNODES*DPAD];
__device__ __align__(16) uint32_t g_BHI[98304];
__device__ __align__(16) uint32_t g_BLO[98304];
__device__ __align__(16) float g_AS[NNODES*2];
__device__ __align__(16) float g_AD[NNODES*2];
__device__ __align__(16) float g_S1[CF];
__device__ __align__(16) float g_S2[CF];
__device__ __align__(16) float g_cs[CF];
__device__ __align__(16) float g_cb[CF];
__device__ int   g_cnt[NNODES];
__device__ int   g_rowptr[NNODES+1];
__device__ int   g_cursor[NNODES];
__device__ int   g_csrc[NEDGES];
__device__ int   g_bsum[32];
__device__ int   g_is64;

// ---------------- bf16 hi/lo split + pack ----------------
__device__ __forceinline__ void split_pack(float e0, float e1,
                                           uint32_t& hp, uint32_t& lp) {
    unsigned short h0 = __bfloat16_as_ushort(__float2bfloat16_rn(e0));
    unsigned short h1 = __bfloat16_as_ushort(__float2bfloat16_rn(e1));
    float f0 = __uint_as_float((uint32_t)h0 << 16);
    float f1 = __uint_as_float((uint32_t)h1 << 16);
    unsigned short l0 = __bfloat16_as_ushort(__float2bfloat16_rn(e0 - f0));
    unsigned short l1 = __bfloat16_as_ushort(__float2bfloat16_rn(e1 - f1));
    hp = (uint32_t)h0 | ((uint32_t)h1 << 16);
    lp = (uint32_t)l0 | ((uint32_t)l1 << 16);
}

__device__ __forceinline__ void mma16816(float& d0, float& d1, float& d2, float& d3,
                                         uint32_t a0, uint32_t a1, uint32_t a2, uint32_t a3,
                                         uint32_t b0, uint32_t b1) {
    asm volatile(
        "mma.sync.aligned.m16n8k16.row.col.f32.bf16.bf16.f32 "
        "{%0,%1,%2,%3}, {%4,%5,%6,%7}, {%8,%9}, {%0,%1,%2,%3};"
        : "+f"(d0), "+f"(d1), "+f"(d2), "+f"(d3)
        : "r"(a0), "r"(a1), "r"(a2), "r"(a3), "r"(b0), "r"(b1));
}

__device__ __forceinline__ int edge_src(const void* p, int e) {
    return g_is64 ? (int)((const long long*)p)[e] : ((const int*)p)[e];
}
__device__ __forceinline__ int edge_dst(const void* p, int e) {
    return g_is64 ? (int)((const long long*)p)[NEDGES + e] : ((const int*)p)[NEDGES + e];
}

// ---------------- init: zero counters + stats, detect edge dtype ----------------
__global__ void init_kernel(const void* idx) {
    int i = blockIdx.x * blockDim.x + threadIdx.x;
    if (i < NNODES) g_cnt[i] = 0;
    if (i < CF) { g_S1[i] = 0.f; g_S2[i] = 0.f; }
    if (blockIdx.x == gridDim.x - 1) {
        const int* w = (const int*)idx;
        __shared__ int nz;
        if (threadIdx.x == 0) nz = 0;
        __syncthreads();
        for (int t = threadIdx.x; t < 4096; t += blockDim.x) {
            long long pos = 2LL * t * (NEDGES / 4096) + 1;
            if (pos < 2LL * NEDGES && w[pos] != 0) atomicOr(&nz, 1);
        }
        __syncthreads();
        if (threadIdx.x == 0) g_is64 = (nz == 0) ? 1 : 0;
    }
}

// ---------------- CSR build ----------------
__global__ void hist_kernel(const void* eidx) {
    int e = blockIdx.x * blockDim.x + threadIdx.x;
    if (e < NEDGES) atomicAdd(&g_cnt[edge_dst(eidx, e)], 1);
}
__global__ void scan1_kernel() {
    __shared__ int ws[32];
    int b = blockIdx.x, tid = threadIdx.x, lane = tid & 31, wid = tid >> 5;
    int i = b * 1024 + tid;
    int v = (i < NNODES) ? g_cnt[i] : 0;
    int x = v;
    #pragma unroll
    for (int o = 1; o < 32; o <<= 1) {
        int y = __shfl_up_sync(0xffffffffu, x, o);
        if (lane >= o) x += y;
    }
    if (lane == 31) ws[wid] = x;
    __syncthreads();
    if (wid == 0) {
        int s = ws[lane];
        #pragma unroll
        for (int o = 1; o < 32; o <<= 1) {
            int y = __shfl_up_sync(0xffffffffu, s, o);
            if (lane >= o) s += y;
        }
        ws[lane] = s;
    }
    __syncthreads();
    int incl = x + (wid > 0 ? ws[wid - 1] : 0);
    if (i < NNODES) g_rowptr[i] = incl - v;
    if (tid == 1023) g_bsum[b] = incl;
}
__global__ void scan3_kernel() {
    int b = blockIdx.x;
    int off = 0;
    #pragma unroll
    for (int j = 0; j < 20; j++) off += (j < b) ? g_bsum[j] : 0;
    int i = b * 1024 + threadIdx.x;
    if (i < NNODES) {
        int r = g_rowptr[i] + off;
        g_rowptr[i] = r;
        g_cursor[i] = r;
    }
    if (b == 0 && threadIdx.x == 0) {
        int t = 0;
        #pragma unroll
        for (int j = 0; j < 20; j++) t += g_bsum[j];
        g_rowptr[NNODES] = t;
    }
}
__global__ void scatter_kernel(const void* eidx) {
    int e = blockIdx.x * blockDim.x + threadIdx.x;
    if (e < NEDGES) {
        int d = edge_dst(eidx, e);
        int s = edge_src(eidx, e);
        int p = atomicAdd(&g_cursor[d], 1);
        g_csrc[p] = s;
    }
}

// ---------------- pad node features 92 -> 128 ----------------
__global__ void pad_nf_kernel(const float* __restrict__ nf) {
    int i = blockIdx.x * blockDim.x + threadIdx.x;
    if (i < NNODES * DPAD) {
        int n = i >> 7, c = i & 127;
        g_NF[i] = (c < DINF) ? nf[n * DINF + c] : 0.f;
    }
}

// ---------------- pack ALL weights in one launch ----------------
__global__ void packall_kernel(const float* __restrict__ We, const float* __restrict__ W1,
                               const float* __restrict__ W2, const float* __restrict__ Wm,
                               const float* __restrict__ Wv, const float* __restrict__ Wg,
                               const float* __restrict__ Wd) {
    int idx = blockIdx.x * blockDim.x + threadIdx.x;
    const float* W; int Kreal, Kpad, N; uint32_t base; int local;
    if      (idx <  8192) { W = We; Kreal = DINF; Kpad = 128; N = 128; base = 0;     local = idx; }
    else if (idx < 16384) { W = W1; Kreal = 128;  Kpad = 128; N = 128; base = 8192;  local = idx - 8192; }
    else if (idx < 24576) { W = W2; Kreal = 128;  Kpad = 128; N = 128; base = 16384; local = idx - 16384; }
    else if (idx < 32768) { W = Wm; Kreal = 128;  Kpad = 128; N = 128; base = 24576; local = idx - 24576; }
    else if (idx < 40960) { W = Wv; Kreal = 128;  Kpad = 128; N = 128; base = 32768; local = idx - 32768; }
    else if (idx < 57344) { W = Wg; Kreal = 128;  Kpad = 128; N = 256; base = 40960; local = idx - 40960; }
    else if (idx < 73728) { W = Wd; Kreal = 256;  Kpad = 256; N = 128; base = 57344; local = idx - 57344; }
    else return;
    int pairs = Kpad >> 1;
    int n = local / pairs, kp = local - n * pairs;
    int nb = n >> 7, nr = n & 127;
    int k0 = 2 * kp;
    float v0 = (k0     < Kreal) ? W[k0 * N + n]       : 0.f;
    float v1 = (k0 + 1 < Kreal) ? W[(k0 + 1) * N + n] : 0.f;
    uint32_t hp, lp;
    split_pack(v0, v1, hp, lp);
    uint32_t off = base + (uint32_t)nb * 128u * pairs + (uint32_t)nr * pairs + kp;
    g_BHI[off] = hp;
    g_BLO[off] = lp;
}

// ================= bf16 3-product mma.sync GEMM (R7 staging) =================
// fp32 out: Out + nb*nbstride + row*ldo + cc. bf16 out (OutBf set): packed bf16x2
// at [row][nb*64 + cc/2] (row stride 128 pairs). bias nb=0; bias2 nb=1.
__global__ void __launch_bounds__(256, 2)
mm_gemm(const float* __restrict__ A, int lda, int Kc, int M,
        uint32_t bbase,
        const float* __restrict__ bias, const float* __restrict__ bias2,
        float* __restrict__ Out, int ldo, int nbstride,
        __nv_bfloat162* __restrict__ OutBf,
        const float* __restrict__ affs, const float* __restrict__ affb,
        int do_stats,
        const float* __restrict__ atts, const float* __restrict__ attd)
{
    __shared__ uint32_t AHI[128 * 20], ALO[128 * 20];
    __shared__ uint32_t BHI[128 * 20], BLO[128 * 20];
    __shared__ float    RED1[128], RED2[128];

    const int tid = threadIdx.x, wid = tid >> 5, lane = tid & 31;
    const int g = lane >> 2, tc = lane & 3;
    const int wm = wid >> 2, wn = wid & 3;
    const int r0 = blockIdx.x * 128;
    const int nb = blockIdx.y;
    const int pairsK = Kc * 16;
    const uint32_t bimg = bbase + (uint32_t)nb * 128u * pairsK;

    float acc[4][4][4];
    #pragma unroll
    for (int mt = 0; mt < 4; mt++)
        #pragma unroll
        for (int nt = 0; nt < 4; nt++)
            #pragma unroll
            for (int q = 0; q < 4; q++) acc[mt][nt][q] = 0.f;

    for (int c = 0; c < Kc; c++) {
        __syncthreads();
        #pragma unroll
        for (int i = 0; i < 8; i++) {
            int idx = i * 256 + tid;
            int row = idx >> 4, p = idx & 15;
            int grow = r0 + row;
            float2 v = make_float2(0.f, 0.f);
            if (grow < M) {
                v = *(const float2*)&A[(size_t)grow * lda + c * 32 + p * 2];
                if (affs) {
                    int k = c * 32 + p * 2;
                    v.x = fmaxf(affs[k    ] * v.x + affb[k    ], 0.f);
                    v.y = fmaxf(affs[k + 1] * v.y + affb[k + 1], 0.f);
                }
            }
            uint32_t hp, lp;
            split_pack(v.x, v.y, hp, lp);
            AHI[row * 20 + p] = hp;
            ALO[row * 20 + p] = lp;
        }
        #pragma unroll
        for (int i = 0; i < 8; i++) {
            int idx = i * 256 + tid;
            int n = idx >> 4, p = idx & 15;
            uint32_t src = bimg + (uint32_t)n * pairsK + c * 16 + p;
            BHI[n * 20 + p] = g_BHI[src];
            BLO[n * 20 + p] = g_BLO[src];
        }
        __syncthreads();

        #pragma unroll
        for (int prod = 0; prod < 3; prod++) {
            const uint32_t* Ab = (prod == 2) ? ALO : AHI;
            const uint32_t* Bb = (prod == 1) ? BLO : BHI;
            #pragma unroll
            for (int ks = 0; ks < 2; ks++) {
                uint32_t af[4][4], bf[4][2];
                #pragma unroll
                for (int mt = 0; mt < 4; mt++) {
                    int rbase = (wm * 64 + mt * 16 + g) * 20 + ks * 8 + tc;
                    af[mt][0] = Ab[rbase];
                    af[mt][1] = Ab[rbase + 8 * 20];
                    af[mt][2] = Ab[rbase + 4];
                    af[mt][3] = Ab[rbase + 8 * 20 + 4];
                }
                #pragma unroll
                for (int nt = 0; nt < 4; nt++) {
                    int nbase = (wn * 32 + nt * 8 + g) * 20 + ks * 8 + tc;
                    bf[nt][0] = Bb[nbase];
                    bf[nt][1] = Bb[nbase + 4];
                }
                #pragma unroll
                for (int mt = 0; mt < 4; mt++)
                    #pragma unroll
                    for (int nt = 0; nt < 4; nt++)
                        mma16816(acc[mt][nt][0], acc[mt][nt][1],
                                 acc[mt][nt][2], acc[mt][nt][3],
                                 af[mt][0], af[mt][1], af[mt][2], af[mt][3],
                                 bf[nt][0], bf[nt][1]);
            }
        }
    }

    // ---- epilogue
    const float* bsel = (nb == 1 && bias2) ? bias2 : bias;
    float bc[4][2];
    #pragma unroll
    for (int nt = 0; nt < 4; nt++) {
        int cc = wn * 32 + nt * 8 + tc * 2;
        bc[nt][0] = bsel ? bsel[cc]     : 0.f;
        bc[nt][1] = bsel ? bsel[cc + 1] : 0.f;
    }

    if (OutBf) {
        #pragma unroll
        for (int mt = 0; mt < 4; mt++) {
            int row0 = r0 + wm * 64 + mt * 16 + g;
            int row1 = row0 + 8;
            #pragma unroll
            for (int nt = 0; nt < 4; nt++) {
                int pidx = nb * 64 + (wn * 32 + nt * 8 + tc * 2) / 2;
                if (row0 < M)
                    OutBf[(size_t)row0 * 128 + pidx] =
                        __floats2bfloat162_rn(acc[mt][nt][0], acc[mt][nt][1]);
                if (row1 < M)
                    OutBf[(size_t)row1 * 128 + pidx] =
                        __floats2bfloat162_rn(acc[mt][nt][2], acc[mt][nt][3]);
            }
        }
    } else {
        float* outp = Out + (size_t)nb * nbstride;
        #pragma unroll
        for (int mt = 0; mt < 4; mt++) {
            int row0 = r0 + wm * 64 + mt * 16 + g;
            int row1 = row0 + 8;
            #pragma unroll
            for (int nt = 0; nt < 4; nt++) {
                int cc = wn * 32 + nt * 8 + tc * 2;
                if (row0 < M) {
                    float2 o = make_float2(acc[mt][nt][0] + bc[nt][0],
                                           acc[mt][nt][1] + bc[nt][1]);
                    *(float2*)&outp[(size_t)row0 * ldo + cc] = o;
                }
                if (row1 < M) {
                    float2 o = make_float2(acc[mt][nt][2] + bc[nt][0],
                                           acc[mt][nt][3] + bc[nt][1]);
                    *(float2*)&outp[(size_t)row1 * ldo + cc] = o;
                }
            }
        }
    }

    if (do_stats) {
        if (tid < CF) { RED1[tid] = 0.f; RED2[tid] = 0.f; }
        __syncthreads();
        #pragma unroll
        for (int nt = 0; nt < 4; nt++) {
            int ccl = wn * 32 + nt * 8 + tc * 2;
            float s0 = 0.f, q0 = 0.f, s1 = 0.f, q1 = 0.f;
            #pragma unroll
            for (int mt = 0; mt < 4; mt++) {
                int row0 = r0 + wm * 64 + mt * 16 + g;
                if (row0 < M) {
                    float v0 = acc[mt][nt][0] + bc[nt][0];
                    float v1 = acc[mt][nt][1] + bc[nt][1];
                    s0 += v0; q0 += v0 * v0; s1 += v1; q1 += v1 * v1;
                }
                if (row0 + 8 < M) {
                    float v0 = acc[mt][nt][2] + bc[nt][0];
                    float v1 = acc[mt][nt][3] + bc[nt][1];
                    s0 += v0; q0 += v0 * v0; s1 += v1; q1 += v1 * v1;
                }
            }
            atomicAdd(&RED1[ccl], s0); atomicAdd(&RED2[ccl], q0);
            atomicAdd(&RED1[ccl + 1], s1); atomicAdd(&RED2[ccl + 1], q1);
        }
        __syncthreads();
        if (tid < CF) { atomicAdd(&g_S1[tid], RED1[tid]); atomicAdd(&g_S2[tid], RED2[tid]); }
    }

    if (atts) {
        if (tid < 128) { RED1[tid] = 0.f; RED2[tid] = 0.f; }
        __syncthreads();
        float avs[4][2], avd[4][2];
        #pragma unroll
        for (int nt = 0; nt < 4; nt++) {
            int cc = wn * 32 + nt * 8 + tc * 2;
            avs[nt][0] = atts[nb * CF + cc]; avs[nt][1] = atts[nb * CF + cc + 1];
            avd[nt][0] = attd[nb * CF + cc]; avd[nt][1] = attd[nb * CF + cc + 1];
        }
        #pragma unroll
        for (int mt = 0; mt < 4; mt++) {
            float ss0 = 0.f, sd0 = 0.f, ss1 = 0.f, sd1 = 0.f;
            #pragma unroll
            for (int nt = 0; nt < 4; nt++) {
                ss0 += acc[mt][nt][0] * avs[nt][0] + acc[mt][nt][1] * avs[nt][1];
                sd0 += acc[mt][nt][0] * avd[nt][0] + acc[mt][nt][1] * avd[nt][1];
                ss1 += acc[mt][nt][2] * avs[nt][0] + acc[mt][nt][3] * avs[nt][1];
                sd1 += acc[mt][nt][2] * avd[nt][0] + acc[mt][nt][3] * avd[nt][1];
            }
            int rl = wm * 64 + mt * 16 + g;
            atomicAdd(&RED1[rl], ss0);     atomicAdd(&RED2[rl], sd0);
            atomicAdd(&RED1[rl + 8], ss1); atomicAdd(&RED2[rl + 8], sd1);
        }
        __syncthreads();
        if (tid < 128 && r0 + tid < M) {
            g_AS[(r0 + tid) * 2 + nb] = RED1[tid];
            g_AD[(r0 + tid) * 2 + nb] = RED2[tid];
        }
    }
}

// ---------------- z = eps*exp(0.5*logvar)+mu ----------------
__global__ void z_kernel(const float* __restrict__ eps, float* __restrict__ out) {
    int i = blockIdx.x * blockDim.x + threadIdx.x;
    if (i < NCF) {
        float mu = out[2 * NCF + i];
        float lv = out[3 * NCF + i];
        out[i] = eps[i] * expf(0.5f * lv) + mu;
    }
}

// ---------------- BN finalize (self-resetting stats) ----------------
__global__ void bn_fin_kernel(const float* __restrict__ gam, const float* __restrict__ bet) {
    int c = threadIdx.x;
    if (c < CF) {
        float s1 = g_S1[c], s2 = g_S2[c];
        float mu  = s1 / (float)NNODES;
        float var = s2 / (float)NNODES - mu * mu;
        float a   = gam[c] * rsqrtf(var + 1e-5f);
        g_cs[c] = a;
        g_cb[c] = bet[c] - mu * a;
        g_S1[c] = 0.f;
        g_S2[c] = 0.f;
    }
}

// ---------------- GIN aggregation (optional fused affine+relu on gathered rows) ----
__global__ void gin_agg_kernel(const float* __restrict__ src,
                               const float* __restrict__ cs,
                               const float* __restrict__ cb) {
    int warp = (blockIdx.x * blockDim.x + threadIdx.x) >> 5;
    int lane = threadIdx.x & 31;
    if (warp >= NNODES) return;
    int n = warp;
    const bool aff = (cs != nullptr);
    float4 sc = make_float4(1.f, 1.f, 1.f, 1.f), bb = make_float4(0.f, 0.f, 0.f, 0.f);
    if (aff) {
        sc = *(const float4*)&cs[lane * 4];
        bb = *(const float4*)&cb[lane * 4];
    }
    float4 acc = *(const float4*)&src[n * CF + lane * 4];
    if (aff) {
        acc.x = fmaxf(sc.x * acc.x + bb.x, 0.f);
        acc.y = fmaxf(sc.y * acc.y + bb.y, 0.f);
        acc.z = fmaxf(sc.z * acc.z + bb.z, 0.f);
        acc.w = fmaxf(sc.w * acc.w + bb.w, 0.f);
    }
    int beg = g_rowptr[n], end = g_rowptr[n + 1];
    int i = beg;
    for (; i + 1 < end; i += 2) {
        int s0 = g_csrc[i], s1v = g_csrc[i + 1];
        float4 v0 = *(const float4*)&src[s0 * CF + lane * 4];
        float4 v1 = *(const float4*)&src[s1v * CF + lane * 4];
        if (aff) {
            v0.x = fmaxf(sc.x * v0.x + bb.x, 0.f); v0.y = fmaxf(sc.y * v0.y + bb.y, 0.f);
            v0.z = fmaxf(sc.z * v0.z + bb.z, 0.f); v0.w = fmaxf(sc.w * v0.w + bb.w, 0.f);
            v1.x = fmaxf(sc.x * v1.x + bb.x, 0.f); v1.y = fmaxf(sc.y * v1.y + bb.y, 0.f);
            v1.z = fmaxf(sc.z * v1.z + bb.z, 0.f); v1.w = fmaxf(sc.w * v1.w + bb.w, 0.f);
        }
        acc.x += v0.x + v1.x; acc.y += v0.y + v1.y;
        acc.z += v0.z + v1.z; acc.w += v0.w + v1.w;
    }
    if (i < end) {
        int s0 = g_csrc[i];
        float4 v0 = *(const float4*)&src[s0 * CF + lane * 4];
        if (aff) {
            v0.x = fmaxf(sc.x * v0.x + bb.x, 0.f); v0.y = fmaxf(sc.y * v0.y + bb.y, 0.f);
            v0.z = fmaxf(sc.z * v0.z + bb.z, 0.f); v0.w = fmaxf(sc.w * v0.w + bb.w, 0.f);
        }
        acc.x += v0.x; acc.y += v0.y; acc.z += v0.z; acc.w += v0.w;
    }
    *(float4*)&g_Hb[n * CF + lane * 4] = acc;
}

__device__ __forceinline__ float lrelu(float x) { return x > 0.f ? x : 0.2f * x; }

__device__ __forceinline__ float4 bf2x2_to_f4(__nv_bfloat162 p0, __nv_bfloat162 p1) {
    return make_float4(__low2float(p0), __high2float(p0),
                       __low2float(p1), __high2float(p1));
}

// ---------------- GAT aggregation: ONE warp per node, BOTH heads (bf16 hh) -----
__global__ void gat_agg_kernel(const float* __restrict__ b_gat) {
    int warp = (blockIdx.x * blockDim.x + threadIdx.x) >> 5;
    int lane = threadIdx.x & 31;
    if (warp >= NNODES) return;
    int n = warp;
    const __nv_bfloat162* hh = (const __nv_bfloat162*)g_HHb;
    float2 ad  = *(const float2*)&g_AD[n * 2];
    float2 asn = *(const float2*)&g_AS[n * 2];
    float ls0 = lrelu(asn.x + ad.x);
    float ls1 = lrelu(asn.y + ad.y);
    int beg = g_rowptr[n], end = g_rowptr[n + 1];

    float m0 = ls0, m1 = ls1;
    for (int i = beg + lane; i < end; i += 32) {
        int s = g_csrc[i];
        float2 a = *(const float2*)&g_AS[s * 2];
        m0 = fmaxf(m0, lrelu(a.x + ad.x));
        m1 = fmaxf(m1, lrelu(a.y + ad.y));
    }
    #pragma unroll
    for (int o = 16; o >= 1; o >>= 1) {
        m0 = fmaxf(m0, __shfl_xor_sync(0xffffffffu, m0, o));
        m1 = fmaxf(m1, __shfl_xor_sync(0xffffffffu, m1, o));
    }

    float w0 = expf(ls0 - m0), w1 = expf(ls1 - m1);
    float s0 = w0, s1 = w1;
    // lane covers channels lane*4..+3: head0 pairs lane*2,+1; head1 pairs 64+lane*2,+1
    const __nv_bfloat162* hn = &hh[(size_t)n * 128];
    float4 h0 = bf2x2_to_f4(hn[lane * 2], hn[lane * 2 + 1]);
    float4 h1 = bf2x2_to_f4(hn[64 + lane * 2], hn[64 + lane * 2 + 1]);
    float4 acc0 = make_float4(w0 * h0.x, w0 * h0.y, w0 * h0.z, w0 * h0.w);
    float4 acc1 = make_float4(w1 * h1.x, w1 * h1.y, w1 * h1.z, w1 * h1.w);
    int i = beg;
    for (; i + 1 < end; i += 2) {
        int sa = g_csrc[i], sb = g_csrc[i + 1];
        float2 aa = *(const float2*)&g_AS[sa * 2];
        float2 ab = *(const float2*)&g_AS[sb * 2];
        float ea0 = expf(lrelu(aa.x + ad.x) - m0), ea1 = expf(lrelu(aa.y + ad.y) - m1);
        float eb0 = expf(lrelu(ab.x + ad.x) - m0), eb1 = expf(lrelu(ab.y + ad.y) - m1);
        s0 += ea0 + eb0; s1 += ea1 + eb1;
        const __nv_bfloat162* ha = &hh[(size_t)sa * 128];
        const __nv_bfloat162* hb2 = &hh[(size_t)sb * 128];
        float4 va0 = bf2x2_to_f4(ha[lane * 2], ha[lane * 2 + 1]);
        float4 va1 = bf2x2_to_f4(ha[64 + lane * 2], ha[64 + lane * 2 + 1]);
        float4 vb0 = bf2x2_to_f4(hb2[lane * 2], hb2[lane * 2 + 1]);
        float4 vb1 = bf2x2_to_f4(hb2[64 + lane * 2], hb2[64 + lane * 2 + 1]);
        acc0.x += ea0 * va0.x + eb0 * vb0.x; acc0.y += ea0 * va0.y + eb0 * vb0.y;
        acc0.z += ea0 * va0.z + eb0 * vb0.z; acc0.w += ea0 * va0.w + eb0 * vb0.w;
        acc1.x += ea1 * va1.x + eb1 * vb1.x; acc1.y += ea1 * va1.y + eb1 * vb1.y;
        acc1.z += ea1 * va1.z + eb1 * vb1.z; acc1.w += ea1 * va1.w + eb1 * vb1.w;
    }
    if (i < end) {
        int sa = g_csrc[i];
        float2 aa = *(const float2*)&g_AS[sa * 2];
        float ea0 = expf(lrelu(aa.x + ad.x) - m0), ea1 = expf(lrelu(aa.y + ad.y) - m1);
        s0 += ea0; s1 += ea1;
        const __nv_bfloat162* ha = &hh[(size_t)sa * 128];
        float4 va0 = bf2x2_to_f4(ha[lane * 2], ha[lane * 2 + 1]);
        float4 va1 = bf2x2_to_f4(ha[64 + lane * 2], ha[64 + lane * 2 + 1]);
        acc0.x += ea0 * va0.x; acc0.y += ea0 * va0.y;
        acc0.z += ea0 * va0.z; acc0.w += ea0 * va0.w;
        acc1.x += ea1 * va1.x; acc1.y += ea1 * va1.y;
        acc1.z += ea1 * va1.z; acc1.w += ea1 * va1.w;
    }
    float i0 = 1.f / s0, i1 = 1.f / s1;
    float4 bg0 = *(const float4*)&b_gat[lane * 4];
    float4 bg1 = *(const float4*)&b_gat[128 + lane * 4];
    float4 o0 = make_float4(acc0.x * i0 + bg0.x, acc0.y * i0 + bg0.y,
                            acc0.z * i0 + bg0.z, acc0.w * i0 + bg0.w);
    float4 o1 = make_float4(acc1.x * i1 + bg1.x, acc1.y * i1 + bg1.y,
                            acc1.z * i1 + bg1.z, acc1.w * i1 + bg1.w);
    *(float4*)&g_AGG[n * 256 + lane * 4]       = o0;
    *(float4*)&g_AGG[n * 256 + 128 + lane * 4] = o1;
}

// ---------------- host orchestration ----------------
extern "C" void kernel_launch(void* const* d_in, const int* in_sizes, int n_in,
                              void* d_out, int out_size) {
    const float* nf     = (const float*)d_in[0];
    const void*  eidx   =               d_in[1];
    const float* eps    = (const float*)d_in[2];
    const float* W_emb  = (const float*)d_in[3];
    const float* b_emb  = (const float*)d_in[4];
    const float* g_embp = (const float*)d_in[5];
    const float* be_emb = (const float*)d_in[6];
    const float* W1     = (const float*)d_in[7];
    const float* b1     = (const float*)d_in[8];
    const float* g1     = (const float*)d_in[9];
    const float* be1    = (const float*)d_in[10];
    const float* W2     = (const float*)d_in[11];
    const float* b2     = (const float*)d_in[12];
    const float* W_mu   = (const float*)d_in[13];
    const float* b_mu   = (const float*)d_in[14];
    const float* W_var  = (const float*)d_in[15];
    const float* b_var  = (const float*)d_in[16];
    const float* W_gat  = (const float*)d_in[17];
    const float* att_s  = (const float*)d_in[18];
    const float* att_d  = (const float*)d_in[19];
    const float* b_gat  = (const float*)d_in[20];
    const float* W_dec  = (const float*)d_in[21];
    const float* b_dec  = (const float*)d_in[22];
    float* out = (float*)d_out;

    float *X, *T, *Hb, *HHp, *AGG, *ZOUT, *CS, *CB, *NF;
    cudaGetSymbolAddress((void**)&X,    g_X);
    cudaGetSymbolAddress((void**)&T,    g_T);
    cudaGetSymbolAddress((void**)&Hb,   g_Hb);
    cudaGetSymbolAddress((void**)&HHp,  g_HHb);
    cudaGetSymbolAddress((void**)&AGG,  g_AGG);
    cudaGetSymbolAddress((void**)&ZOUT, g_ZOUT);
    cudaGetSymbolAddress((void**)&CS,   g_cs);
    cudaGetSymbolAddress((void**)&CB,   g_cb);
    cudaGetSymbolAddress((void**)&NF,   g_NF);

    const int GX = (NNODES + 127) / 128;   // 157
    dim3 grid1(GX, 1), grid2(GX, 2);
    const int EB = (NEDGES + 255) / 256;
    const int NB = (NNODES + 255) / 256;
    const int WARP_N = (NNODES * 32 + 255) / 256;
    const int PB  = (NNODES * DPAD + 255) / 256;
    const int ELB = (NCF + 255) / 256;

    const uint32_t O_EMB = 0, O_W1 = 8192, O_W2 = 16384, O_MU = 24576,
                   O_GAT = 40960, O_DEC = 57344;

    packall_kernel<<<(73728 + 255) / 256, 256>>>(W_emb, W1, W2, W_mu, W_var, W_gat, W_dec);
    pad_nf_kernel<<<PB, 256>>>(nf);
    init_kernel<<<NB, 256>>>(eidx);
    hist_kernel<<<EB, 256>>>(eidx);
    scan1_kernel<<<20, 1024>>>();
    // 6th launch: atom embedding GEMM (ncu -s 5 target)
    mm_gemm<<<grid1, 256>>>(NF, DPAD, 4, NNODES, O_EMB, b_emb, nullptr, T, CF, 0,
                            nullptr, nullptr, nullptr, 1, nullptr, nullptr);
    scan3_kernel<<<20, 1024>>>();
    scatter_kernel<<<EB, 256>>>(eidx);
    bn_fin_kernel<<<1, 128>>>(g_embp, be_emb);

    // GIN layer 0 (agg applies emb-BN affine+relu to gathered rows of T)
    gin_agg_kernel<<<WARP_N, 256>>>(T, CS, CB);
    mm_gemm<<<grid1, 256>>>(Hb, CF, 4, NNODES, O_W1, b1, nullptr, T, CF, 0,
                            nullptr, nullptr, nullptr, 1, nullptr, nullptr);
    bn_fin_kernel<<<1, 128>>>(g1, be1);
    mm_gemm<<<grid1, 256>>>(T, CF, 4, NNODES, O_W2, b2, nullptr, X, CF, 0,
                            nullptr, CS, CB, 0, nullptr, nullptr);

    // GIN layer 1 (raw x)
    gin_agg_kernel<<<WARP_N, 256>>>(X, nullptr, nullptr);
    mm_gemm<<<grid1, 256>>>(Hb, CF, 4, NNODES, O_W1, b1, nullptr, T, CF, 0,
                            nullptr, nullptr, nullptr, 1, nullptr, nullptr);
    bn_fin_kernel<<<1, 128>>>(g1, be1);
    mm_gemm<<<grid1, 256>>>(T, CF, 4, NNODES, O_W2, b2, nullptr, X, CF, 0,
                            nullptr, CS, CB, 0, nullptr, nullptr);

    // VAE heads merged: nb=0 -> mu (out+2NCF), nb=1 -> logvar (out+3NCF)
    mm_gemm<<<grid2, 256>>>(X, CF, 4, NNODES, O_MU, b_mu, b_var,
                            out + 2 * NCF, CF, NCF,
                            nullptr, nullptr, nullptr, 0, nullptr, nullptr);
    z_kernel<<<ELB, 256>>>(eps, out);

    // GAT decoder x2 (shared weights); hh stored bf16
    for (int l = 0; l < 2; l++) {
        const float* zcur = (l == 0) ? out : ZOUT;
        float* zdst       = (l == 0) ? ZOUT : out + NCF;
        mm_gemm<<<grid2, 256>>>(zcur, CF, 4, NNODES, O_GAT, nullptr, nullptr,
                                nullptr, 0, 0, (__nv_bfloat162*)HHp,
                                nullptr, nullptr, 0, att_s, att_d);
        gat_agg_kernel<<<WARP_N, 256>>>(b_gat);
        mm_gemm<<<grid1, 256>>>(AGG, 256, 8, NNODES, O_DEC, b_dec, nullptr, zdst, CF, 0,
                                nullptr, nullptr, nullptr, 0, nullptr, nullptr);
    }
    (void)in_sizes; (void)n_in; (void)out_size;
}

// round 11
// speedup vs baseline: 1.1406x; 1.0059x over previous
#include <cuda_runtime.h>
#include <cuda_bf16.h>
#include <cuda_fp16.h>
#include <cstdint>

#define NNODES 20000
#define NEDGES 640000
#define DINF   92
#define DPAD   128
#define CF     128
#define NCF    (NNODES*CF)

// ---------------- scratch (device globals; no allocation) ----------------
__device__ __align__(16) float g_X[NCF];
__device__ __align__(16) float g_T[NCF];
__device__ __align__(16) float g_Hb[NCF];
__device__ __align__(16) float g_HHb[NNODES*128];   // half2: [n][128 pairs] = 256 ch
__device__ __align__(16) float g_AGG[NNODES*256];
__device__ __align__(16) float g_ZOUT[NCF];
__device__ __align__(16) float g_NF[NNODES*DPAD];
__device__ __align__(16) uint32_t g_BHI[98304];
__device__ __align__(16) uint32_t g_BLO[98304];
__device__ __align__(16) float g_AS[NNODES*2];
__device__ __align__(16) float g_AD[NNODES*2];
__device__ __align__(16) float g_S1[CF];
__device__ __align__(16) float g_S2[CF];
__device__ __align__(16) float g_cs[CF];
__device__ __align__(16) float g_cb[CF];
__device__ int   g_cnt[NNODES];
__device__ int   g_rowptr[NNODES+1];
__device__ int   g_cursor[NNODES];
__device__ int   g_csrc[NEDGES];
__device__ int   g_bsum[32];
__device__ int   g_is64;

// ---------------- bf16 hi/lo split + pack ----------------
__device__ __forceinline__ void split_pack(float e0, float e1,
                                           uint32_t& hp, uint32_t& lp) {
    unsigned short h0 = __bfloat16_as_ushort(__float2bfloat16_rn(e0));
    unsigned short h1 = __bfloat16_as_ushort(__float2bfloat16_rn(e1));
    float f0 = __uint_as_float((uint32_t)h0 << 16);
    float f1 = __uint_as_float((uint32_t)h1 << 16);
    unsigned short l0 = __bfloat16_as_ushort(__float2bfloat16_rn(e0 - f0));
    unsigned short l1 = __bfloat16_as_ushort(__float2bfloat16_rn(e1 - f1));
    hp = (uint32_t)h0 | ((uint32_t)h1 << 16);
    lp = (uint32_t)l0 | ((uint32_t)l1 << 16);
}

__device__ __forceinline__ void mma16816(float& d0, float& d1, float& d2, float& d3,
                                         uint32_t a0, uint32_t a1, uint32_t a2, uint32_t a3,
                                         uint32_t b0, uint32_t b1) {
    asm volatile(
        "mma.sync.aligned.m16n8k16.row.col.f32.bf16.bf16.f32 "
        "{%0,%1,%2,%3}, {%4,%5,%6,%7}, {%8,%9}, {%0,%1,%2,%3};"
        : "+f"(d0), "+f"(d1), "+f"(d2), "+f"(d3)
        : "r"(a0), "r"(a1), "r"(a2), "r"(a3), "r"(b0), "r"(b1));
}

__device__ __forceinline__ int edge_src(const void* p, int e) {
    return g_is64 ? (int)((const long long*)p)[e] : ((const int*)p)[e];
}
__device__ __forceinline__ int edge_dst(const void* p, int e) {
    return g_is64 ? (int)((const long long*)p)[NEDGES + e] : ((const int*)p)[NEDGES + e];
}

// ---------------- init: zero counters + stats, detect edge dtype ----------------
__global__ void init_kernel(const void* idx) {
    int i = blockIdx.x * blockDim.x + threadIdx.x;
    if (i < NNODES) g_cnt[i] = 0;
    if (i < CF) { g_S1[i] = 0.f; g_S2[i] = 0.f; }
    if (blockIdx.x == gridDim.x - 1) {
        const int* w = (const int*)idx;
        __shared__ int nz;
        if (threadIdx.x == 0) nz = 0;
        __syncthreads();
        for (int t = threadIdx.x; t < 4096; t += blockDim.x) {
            long long pos = 2LL * t * (NEDGES / 4096) + 1;
            if (pos < 2LL * NEDGES && w[pos] != 0) atomicOr(&nz, 1);
        }
        __syncthreads();
        if (threadIdx.x == 0) g_is64 = (nz == 0) ? 1 : 0;
    }
}

// ---------------- CSR build ----------------
__global__ void hist_kernel(const void* eidx) {
    int e = blockIdx.x * blockDim.x + threadIdx.x;
    if (e < NEDGES) atomicAdd(&g_cnt[edge_dst(eidx, e)], 1);
}
__global__ void scan1_kernel() {
    __shared__ int ws[32];
    int b = blockIdx.x, tid = threadIdx.x, lane = tid & 31, wid = tid >> 5;
    int i = b * 1024 + tid;
    int v = (i < NNODES) ? g_cnt[i] : 0;
    int x = v;
    #pragma unroll
    for (int o = 1; o < 32; o <<= 1) {
        int y = __shfl_up_sync(0xffffffffu, x, o);
        if (lane >= o) x += y;
    }
    if (lane == 31) ws[wid] = x;
    __syncthreads();
    if (wid == 0) {
        int s = ws[lane];
        #pragma unroll
        for (int o = 1; o < 32; o <<= 1) {
            int y = __shfl_up_sync(0xffffffffu, s, o);
            if (lane >= o) s += y;
        }
        ws[lane] = s;
    }
    __syncthreads();
    int incl = x + (wid > 0 ? ws[wid - 1] : 0);
    if (i < NNODES) g_rowptr[i] = incl - v;
    if (tid == 1023) g_bsum[b] = incl;
}
__global__ void scan3_kernel() {
    int b = blockIdx.x;
    int off = 0;
    #pragma unroll
    for (int j = 0; j < 20; j++) off += (j < b) ? g_bsum[j] : 0;
    int i = b * 1024 + threadIdx.x;
    if (i < NNODES) {
        int r = g_rowptr[i] + off;
        g_rowptr[i] = r;
        g_cursor[i] = r;
    }
    if (b == 0 && threadIdx.x == 0) {
        int t = 0;
        #pragma unroll
        for (int j = 0; j < 20; j++) t += g_bsum[j];
        g_rowptr[NNODES] = t;
    }
}
__global__ void scatter_kernel(const void* eidx) {
    int e = blockIdx.x * blockDim.x + threadIdx.x;
    if (e < NEDGES) {
        int d = edge_dst(eidx, e);
        int s = edge_src(eidx, e);
        int p = atomicAdd(&g_cursor[d], 1);
        g_csrc[p] = s;
    }
}

// ---------------- pad node features 92 -> 128 ----------------
__global__ void pad_nf_kernel(const float* __restrict__ nf) {
    int i = blockIdx.x * blockDim.x + threadIdx.x;
    if (i < NNODES * DPAD) {
        int n = i >> 7, c = i & 127;
        g_NF[i] = (c < DINF) ? nf[n * DINF + c] : 0.f;
    }
}

// ---------------- pack ALL weights in one launch ----------------
__global__ void packall_kernel(const float* __restrict__ We, const float* __restrict__ W1,
                               const float* __restrict__ W2, const float* __restrict__ Wm,
                               const float* __restrict__ Wv, const float* __restrict__ Wg,
                               const float* __restrict__ Wd) {
    int idx = blockIdx.x * blockDim.x + threadIdx.x;
    const float* W; int Kreal, Kpad, N; uint32_t base; int local;
    if      (idx <  8192) { W = We; Kreal = DINF; Kpad = 128; N = 128; base = 0;     local = idx; }
    else if (idx < 16384) { W = W1; Kreal = 128;  Kpad = 128; N = 128; base = 8192;  local = idx - 8192; }
    else if (idx < 24576) { W = W2; Kreal = 128;  Kpad = 128; N = 128; base = 16384; local = idx - 16384; }
    else if (idx < 32768) { W = Wm; Kreal = 128;  Kpad = 128; N = 128; base = 24576; local = idx - 24576; }
    else if (idx < 40960) { W = Wv; Kreal = 128;  Kpad = 128; N = 128; base = 32768; local = idx - 32768; }
    else if (idx < 57344) { W = Wg; Kreal = 128;  Kpad = 128; N = 256; base = 40960; local = idx - 40960; }
    else if (idx < 73728) { W = Wd; Kreal = 256;  Kpad = 256; N = 128; base = 57344; local = idx - 57344; }
    else return;
    int pairs = Kpad >> 1;
    int n = local / pairs, kp = local - n * pairs;
    int nb = n >> 7, nr = n & 127;
    int k0 = 2 * kp;
    float v0 = (k0     < Kreal) ? W[k0 * N + n]       : 0.f;
    float v1 = (k0 + 1 < Kreal) ? W[(k0 + 1) * N + n] : 0.f;
    uint32_t hp, lp;
    split_pack(v0, v1, hp, lp);
    uint32_t off = base + (uint32_t)nb * 128u * pairs + (uint32_t)nr * pairs + kp;
    g_BHI[off] = hp;
    g_BLO[off] = lp;
}

// ================= bf16 3-product mma.sync GEMM =================
// fp32 out: Out + nb*nbstride + row*ldo + cc. fp16 out (OutHf set): packed half2
// at [row][nb*64 + cc/2] (row stride 128 pairs). bias nb=0; bias2 nb=1.
__global__ void __launch_bounds__(256, 2)
mm_gemm(const float* __restrict__ A, int lda, int Kc, int M,
        uint32_t bbase,
        const float* __restrict__ bias, const float* __restrict__ bias2,
        float* __restrict__ Out, int ldo, int nbstride,
        __half2* __restrict__ OutHf,
        const float* __restrict__ affs, const float* __restrict__ affb,
        int do_stats,
        const float* __restrict__ atts, const float* __restrict__ attd)
{
    __shared__ uint32_t AHI[128 * 20], ALO[128 * 20];
    __shared__ uint32_t BHI[128 * 20], BLO[128 * 20];
    __shared__ float    RED1[128], RED2[128];

    const int tid = threadIdx.x, wid = tid >> 5, lane = tid & 31;
    const int g = lane >> 2, tc = lane & 3;
    const int wm = wid >> 2, wn = wid & 3;
    const int r0 = blockIdx.x * 128;
    const int nb = blockIdx.y;
    const int pairsK = Kc * 16;
    const uint32_t bimg = bbase + (uint32_t)nb * 128u * pairsK;

    float acc[4][4][4];
    #pragma unroll
    for (int mt = 0; mt < 4; mt++)
        #pragma unroll
        for (int nt = 0; nt < 4; nt++)
            #pragma unroll
            for (int q = 0; q < 4; q++) acc[mt][nt][q] = 0.f;

    for (int c = 0; c < Kc; c++) {
        __syncthreads();
        #pragma unroll
        for (int i = 0; i < 8; i++) {
            int idx = i * 256 + tid;
            int row = idx >> 4, p = idx & 15;
            int grow = r0 + row;
            float2 v = make_float2(0.f, 0.f);
            if (grow < M) {
                v = *(const float2*)&A[(size_t)grow * lda + c * 32 + p * 2];
                if (affs) {
                    int k = c * 32 + p * 2;
                    v.x = fmaxf(affs[k    ] * v.x + affb[k    ], 0.f);
                    v.y = fmaxf(affs[k + 1] * v.y + affb[k + 1], 0.f);
                }
            }
            uint32_t hp, lp;
            split_pack(v.x, v.y, hp, lp);
            AHI[row * 20 + p] = hp;
            ALO[row * 20 + p] = lp;
        }
        #pragma unroll
        for (int i = 0; i < 8; i++) {
            int idx = i * 256 + tid;
            int n = idx >> 4, p = idx & 15;
            uint32_t src = bimg + (uint32_t)n * pairsK + c * 16 + p;
            BHI[n * 20 + p] = g_BHI[src];
            BLO[n * 20 + p] = g_BLO[src];
        }
        __syncthreads();

        #pragma unroll
        for (int prod = 0; prod < 3; prod++) {
            const uint32_t* Ab = (prod == 2) ? ALO : AHI;
            const uint32_t* Bb = (prod == 1) ? BLO : BHI;
            #pragma unroll
            for (int ks = 0; ks < 2; ks++) {
                uint32_t af[4][4], bf[4][2];
                #pragma unroll
                for (int mt = 0; mt < 4; mt++) {
                    int rbase = (wm * 64 + mt * 16 + g) * 20 + ks * 8 + tc;
                    af[mt][0] = Ab[rbase];
                    af[mt][1] = Ab[rbase + 8 * 20];
                    af[mt][2] = Ab[rbase + 4];
                    af[mt][3] = Ab[rbase + 8 * 20 + 4];
                }
                #pragma unroll
                for (int nt = 0; nt < 4; nt++) {
                    int nbase = (wn * 32 + nt * 8 + g) * 20 + ks * 8 + tc;
                    bf[nt][0] = Bb[nbase];
                    bf[nt][1] = Bb[nbase + 4];
                }
                #pragma unroll
                for (int mt = 0; mt < 4; mt++)
                    #pragma unroll
                    for (int nt = 0; nt < 4; nt++)
                        mma16816(acc[mt][nt][0], acc[mt][nt][1],
                                 acc[mt][nt][2], acc[mt][nt][3],
                                 af[mt][0], af[mt][1], af[mt][2], af[mt][3],
                                 bf[nt][0], bf[nt][1]);
            }
        }
    }

    // ---- epilogue
    const float* bsel = (nb == 1 && bias2) ? bias2 : bias;
    float bc[4][2];
    #pragma unroll
    for (int nt = 0; nt < 4; nt++) {
        int cc = wn * 32 + nt * 8 + tc * 2;
        bc[nt][0] = bsel ? bsel[cc]     : 0.f;
        bc[nt][1] = bsel ? bsel[cc + 1] : 0.f;
    }

    if (OutHf) {
        #pragma unroll
        for (int mt = 0; mt < 4; mt++) {
            int row0 = r0 + wm * 64 + mt * 16 + g;
            int row1 = row0 + 8;
            #pragma unroll
            for (int nt = 0; nt < 4; nt++) {
                int pidx = nb * 64 + (wn * 32 + nt * 8 + tc * 2) / 2;
                if (row0 < M)
                    OutHf[(size_t)row0 * 128 + pidx] =
                        __floats2half2_rn(acc[mt][nt][0], acc[mt][nt][1]);
                if (row1 < M)
                    OutHf[(size_t)row1 * 128 + pidx] =
                        __floats2half2_rn(acc[mt][nt][2], acc[mt][nt][3]);
            }
        }
    } else {
        float* outp = Out + (size_t)nb * nbstride;
        #pragma unroll
        for (int mt = 0; mt < 4; mt++) {
            int row0 = r0 + wm * 64 + mt * 16 + g;
            int row1 = row0 + 8;
            #pragma unroll
            for (int nt = 0; nt < 4; nt++) {
                int cc = wn * 32 + nt * 8 + tc * 2;
                if (row0 < M) {
                    float2 o = make_float2(acc[mt][nt][0] + bc[nt][0],
                                           acc[mt][nt][1] + bc[nt][1]);
                    *(float2*)&outp[(size_t)row0 * ldo + cc] = o;
                }
                if (row1 < M) {
                    float2 o = make_float2(acc[mt][nt][2] + bc[nt][0],
                                           acc[mt][nt][3] + bc[nt][1]);
                    *(float2*)&outp[(size_t)row1 * ldo + cc] = o;
                }
            }
        }
    }

    if (do_stats) {
        if (tid < CF) { RED1[tid] = 0.f; RED2[tid] = 0.f; }
        __syncthreads();
        #pragma unroll
        for (int nt = 0; nt < 4; nt++) {
            int ccl = wn * 32 + nt * 8 + tc * 2;
            float s0 = 0.f, q0 = 0.f, s1 = 0.f, q1 = 0.f;
            #pragma unroll
            for (int mt = 0; mt < 4; mt++) {
                int row0 = r0 + wm * 64 + mt * 16 + g;
                if (row0 < M) {
                    float v0 = acc[mt][nt][0] + bc[nt][0];
                    float v1 = acc[mt][nt][1] + bc[nt][1];
                    s0 += v0; q0 += v0 * v0; s1 += v1; q1 += v1 * v1;
                }
                if (row0 + 8 < M) {
                    float v0 = acc[mt][nt][2] + bc[nt][0];
                    float v1 = acc[mt][nt][3] + bc[nt][1];
                    s0 += v0; q0 += v0 * v0; s1 += v1; q1 += v1 * v1;
                }
            }
            atomicAdd(&RED1[ccl], s0); atomicAdd(&RED2[ccl], q0);
            atomicAdd(&RED1[ccl + 1], s1); atomicAdd(&RED2[ccl + 1], q1);
        }
        __syncthreads();
        if (tid < CF) { atomicAdd(&g_S1[tid], RED1[tid]); atomicAdd(&g_S2[tid], RED2[tid]); }
    }

    if (atts) {
        if (tid < 128) { RED1[tid] = 0.f; RED2[tid] = 0.f; }
        __syncthreads();
        float avs[4][2], avd[4][2];
        #pragma unroll
        for (int nt = 0; nt < 4; nt++) {
            int cc = wn * 32 + nt * 8 + tc * 2;
            avs[nt][0] = atts[nb * CF + cc]; avs[nt][1] = atts[nb * CF + cc + 1];
            avd[nt][0] = attd[nb * CF + cc]; avd[nt][1] = attd[nb * CF + cc + 1];
        }
        #pragma unroll
        for (int mt = 0; mt < 4; mt++) {
            float ss0 = 0.f, sd0 = 0.f, ss1 = 0.f, sd1 = 0.f;
            #pragma unroll
            for (int nt = 0; nt < 4; nt++) {
                ss0 += acc[mt][nt][0] * avs[nt][0] + acc[mt][nt][1] * avs[nt][1];
                sd0 += acc[mt][nt][0] * avd[nt][0] + acc[mt][nt][1] * avd[nt][1];
                ss1 += acc[mt][nt][2] * avs[nt][0] + acc[mt][nt][3] * avs[nt][1];
                sd1 += acc[mt][nt][2] * avd[nt][0] + acc[mt][nt][3] * avd[nt][1];
            }
            int rl = wm * 64 + mt * 16 + g;
            atomicAdd(&RED1[rl], ss0);     atomicAdd(&RED2[rl], sd0);
            atomicAdd(&RED1[rl + 8], ss1); atomicAdd(&RED2[rl + 8], sd1);
        }
        __syncthreads();
        if (tid < 128 && r0 + tid < M) {
            g_AS[(r0 + tid) * 2 + nb] = RED1[tid];
            g_AD[(r0 + tid) * 2 + nb] = RED2[tid];
        }
    }
}

// ---------------- z = eps*exp(0.5*logvar)+mu ----------------
__global__ void z_kernel(const float* __restrict__ eps, float* __restrict__ out) {
    int i = blockIdx.x * blockDim.x + threadIdx.x;
    if (i < NCF) {
        float mu = out[2 * NCF + i];
        float lv = out[3 * NCF + i];
        out[i] = eps[i] * expf(0.5f * lv) + mu;
    }
}

// ---------------- BN finalize (self-resetting stats) ----------------
__global__ void bn_fin_kernel(const float* __restrict__ gam, const float* __restrict__ bet) {
    int c = threadIdx.x;
    if (c < CF) {
        float s1 = g_S1[c], s2 = g_S2[c];
        float mu  = s1 / (float)NNODES;
        float var = s2 / (float)NNODES - mu * mu;
        float a   = gam[c] * rsqrtf(var + 1e-5f);
        g_cs[c] = a;
        g_cb[c] = bet[c] - mu * a;
        g_S1[c] = 0.f;
        g_S2[c] = 0.f;
    }
}

// ---------------- GIN aggregation (optional fused affine+relu on gathered rows) ----
__global__ void gin_agg_kernel(const float* __restrict__ src,
                               const float* __restrict__ cs,
                               const float* __restrict__ cb) {
    int warp = (blockIdx.x * blockDim.x + threadIdx.x) >> 5;
    int lane = threadIdx.x & 31;
    if (warp >= NNODES) return;
    int n = warp;
    const bool aff = (cs != nullptr);
    float4 sc = make_float4(1.f, 1.f, 1.f, 1.f), bb = make_float4(0.f, 0.f, 0.f, 0.f);
    if (aff) {
        sc = *(const float4*)&cs[lane * 4];
        bb = *(const float4*)&cb[lane * 4];
    }
    float4 acc = *(const float4*)&src[n * CF + lane * 4];
    if (aff) {
        acc.x = fmaxf(sc.x * acc.x + bb.x, 0.f);
        acc.y = fmaxf(sc.y * acc.y + bb.y, 0.f);
        acc.z = fmaxf(sc.z * acc.z + bb.z, 0.f);
        acc.w = fmaxf(sc.w * acc.w + bb.w, 0.f);
    }
    int beg = g_rowptr[n], end = g_rowptr[n + 1];
    int i = beg;
    for (; i + 1 < end; i += 2) {
        int s0 = g_csrc[i], s1v = g_csrc[i + 1];
        float4 v0 = *(const float4*)&src[s0 * CF + lane * 4];
        float4 v1 = *(const float4*)&src[s1v * CF + lane * 4];
        if (aff) {
            v0.x = fmaxf(sc.x * v0.x + bb.x, 0.f); v0.y = fmaxf(sc.y * v0.y + bb.y, 0.f);
            v0.z = fmaxf(sc.z * v0.z + bb.z, 0.f); v0.w = fmaxf(sc.w * v0.w + bb.w, 0.f);
            v1.x = fmaxf(sc.x * v1.x + bb.x, 0.f); v1.y = fmaxf(sc.y * v1.y + bb.y, 0.f);
            v1.z = fmaxf(sc.z * v1.z + bb.z, 0.f); v1.w = fmaxf(sc.w * v1.w + bb.w, 0.f);
        }
        acc.x += v0.x + v1.x; acc.y += v0.y + v1.y;
        acc.z += v0.z + v1.z; acc.w += v0.w + v1.w;
    }
    if (i < end) {
        int s0 = g_csrc[i];
        float4 v0 = *(const float4*)&src[s0 * CF + lane * 4];
        if (aff) {
            v0.x = fmaxf(sc.x * v0.x + bb.x, 0.f); v0.y = fmaxf(sc.y * v0.y + bb.y, 0.f);
            v0.z = fmaxf(sc.z * v0.z + bb.z, 0.f); v0.w = fmaxf(sc.w * v0.w + bb.w, 0.f);
        }
        acc.x += v0.x; acc.y += v0.y; acc.z += v0.z; acc.w += v0.w;
    }
    *(float4*)&g_Hb[n * CF + lane * 4] = acc;
}

__device__ __forceinline__ float lrelu(float x) { return x > 0.f ? x : 0.2f * x; }

__device__ __forceinline__ float4 h2x2_to_f4(__half2 p0, __half2 p1) {
    float2 a = __half22float2(p0), b = __half22float2(p1);
    return make_float4(a.x, a.y, b.x, b.y);
}

// ---------------- GAT aggregation: ONE warp per node, BOTH heads (fp16 hh) -----
__global__ void gat_agg_kernel(const float* __restrict__ b_gat) {
    int warp = (blockIdx.x * blockDim.x + threadIdx.x) >> 5;
    int lane = threadIdx.x & 31;
    if (warp >= NNODES) return;
    int n = warp;
    const __half2* hh = (const __half2*)g_HHb;
    float2 ad  = *(const float2*)&g_AD[n * 2];
    float2 asn = *(const float2*)&g_AS[n * 2];
    float ls0 = lrelu(asn.x + ad.x);
    float ls1 = lrelu(asn.y + ad.y);
    int beg = g_rowptr[n], end = g_rowptr[n + 1];

    float m0 = ls0, m1 = ls1;
    for (int i = beg + lane; i < end; i += 32) {
        int s = g_csrc[i];
        float2 a = *(const float2*)&g_AS[s * 2];
        m0 = fmaxf(m0, lrelu(a.x + ad.x));
        m1 = fmaxf(m1, lrelu(a.y + ad.y));
    }
    #pragma unroll
    for (int o = 16; o >= 1; o >>= 1) {
        m0 = fmaxf(m0, __shfl_xor_sync(0xffffffffu, m0, o));
        m1 = fmaxf(m1, __shfl_xor_sync(0xffffffffu, m1, o));
    }

    float w0 = expf(ls0 - m0), w1 = expf(ls1 - m1);
    float s0 = w0, s1 = w1;
    const __half2* hn = &hh[(size_t)n * 128];
    float4 h0 = h2x2_to_f4(hn[lane * 2], hn[lane * 2 + 1]);
    float4 h1 = h2x2_to_f4(hn[64 + lane * 2], hn[64 + lane * 2 + 1]);
    float4 acc0 = make_float4(w0 * h0.x, w0 * h0.y, w0 * h0.z, w0 * h0.w);
    float4 acc1 = make_float4(w1 * h1.x, w1 * h1.y, w1 * h1.z, w1 * h1.w);
    int i = beg;
    for (; i + 1 < end; i += 2) {
        int sa = g_csrc[i], sb = g_csrc[i + 1];
        float2 aa = *(const float2*)&g_AS[sa * 2];
        float2 ab = *(const float2*)&g_AS[sb * 2];
        float ea0 = expf(lrelu(aa.x + ad.x) - m0), ea1 = expf(lrelu(aa.y + ad.y) - m1);
        float eb0 = expf(lrelu(ab.x + ad.x) - m0), eb1 = expf(lrelu(ab.y + ad.y) - m1);
        s0 += ea0 + eb0; s1 += ea1 + eb1;
        const __half2* ha = &hh[(size_t)sa * 128];
        const __half2* hb2 = &hh[(size_t)sb * 128];
        float4 va0 = h2x2_to_f4(ha[lane * 2], ha[lane * 2 + 1]);
        float4 va1 = h2x2_to_f4(ha[64 + lane * 2], ha[64 + lane * 2 + 1]);
        float4 vb0 = h2x2_to_f4(hb2[lane * 2], hb2[lane * 2 + 1]);
        float4 vb1 = h2x2_to_f4(hb2[64 + lane * 2], hb2[64 + lane * 2 + 1]);
        acc0.x += ea0 * va0.x + eb0 * vb0.x; acc0.y += ea0 * va0.y + eb0 * vb0.y;
        acc0.z += ea0 * va0.z + eb0 * vb0.z; acc0.w += ea0 * va0.w + eb0 * vb0.w;
        acc1.x += ea1 * va1.x + eb1 * vb1.x; acc1.y += ea1 * va1.y + eb1 * vb1.y;
        acc1.z += ea1 * va1.z + eb1 * vb1.z; acc1.w += ea1 * va1.w + eb1 * vb1.w;
    }
    if (i < end) {
        int sa = g_csrc[i];
        float2 aa = *(const float2*)&g_AS[sa * 2];
        float ea0 = expf(lrelu(aa.x + ad.x) - m0), ea1 = expf(lrelu(aa.y + ad.y) - m1);
        s0 += ea0; s1 += ea1;
        const __half2* ha = &hh[(size_t)sa * 128];
        float4 va0 = h2x2_to_f4(ha[lane * 2], ha[lane * 2 + 1]);
        float4 va1 = h2x2_to_f4(ha[64 + lane * 2], ha[64 + lane * 2 + 1]);
        acc0.x += ea0 * va0.x; acc0.y += ea0 * va0.y;
        acc0.z += ea0 * va0.z; acc0.w += ea0 * va0.w;
        acc1.x += ea1 * va1.x; acc1.y += ea1 * va1.y;
        acc1.z += ea1 * va1.z; acc1.w += ea1 * va1.w;
    }
    float i0 = 1.f / s0, i1 = 1.f / s1;
    float4 bg0 = *(const float4*)&b_gat[lane * 4];
    float4 bg1 = *(const float4*)&b_gat[128 + lane * 4];
    float4 o0 = make_float4(acc0.x * i0 + bg0.x, acc0.y * i0 + bg0.y,
                            acc0.z * i0 + bg0.z, acc0.w * i0 + bg0.w);
    float4 o1 = make_float4(acc1.x * i1 + bg1.x, acc1.y * i1 + bg1.y,
                            acc1.z * i1 + bg1.z, acc1.w * i1 + bg1.w);
    *(float4*)&g_AGG[n * 256 + lane * 4]       = o0;
    *(float4*)&g_AGG[n * 256 + 128 + lane * 4] = o1;
}

// ---------------- host orchestration ----------------
extern "C" void kernel_launch(void* const* d_in, const int* in_sizes, int n_in,
                              void* d_out, int out_size) {
    const float* nf     = (const float*)d_in[0];
    const void*  eidx   =               d_in[1];
    const float* eps    = (const float*)d_in[2];
    const float* W_emb  = (const float*)d_in[3];
    const float* b_emb  = (const float*)d_in[4];
    const float* g_embp = (const float*)d_in[5];
    const float* be_emb = (const float*)d_in[6];
    const float* W1     = (const float*)d_in[7];
    const float* b1     = (const float*)d_in[8];
    const float* g1     = (const float*)d_in[9];
    const float* be1    = (const float*)d_in[10];
    const float* W2     = (const float*)d_in[11];
    const float* b2     = (const float*)d_in[12];
    const float* W_mu   = (const float*)d_in[13];
    const float* b_mu   = (const float*)d_in[14];
    const float* W_var  = (const float*)d_in[15];
    const float* b_var  = (const float*)d_in[16];
    const float* W_gat  = (const float*)d_in[17];
    const float* att_s  = (const float*)d_in[18];
    const float* att_d  = (const float*)d_in[19];
    const float* b_gat  = (const float*)d_in[20];
    const float* W_dec  = (const float*)d_in[21];
    const float* b_dec  = (const float*)d_in[22];
    float* out = (float*)d_out;

    float *X, *T, *Hb, *HHp, *AGG, *ZOUT, *CS, *CB, *NF;
    cudaGetSymbolAddress((void**)&X,    g_X);
    cudaGetSymbolAddress((void**)&T,    g_T);
    cudaGetSymbolAddress((void**)&Hb,   g_Hb);
    cudaGetSymbolAddress((void**)&HHp,  g_HHb);
    cudaGetSymbolAddress((void**)&AGG,  g_AGG);
    cudaGetSymbolAddress((void**)&ZOUT, g_ZOUT);
    cudaGetSymbolAddress((void**)&CS,   g_cs);
    cudaGetSymbolAddress((void**)&CB,   g_cb);
    cudaGetSymbolAddress((void**)&NF,   g_NF);

    const int GX = (NNODES + 127) / 128;   // 157
    dim3 grid1(GX, 1), grid2(GX, 2);
    const int EB = (NEDGES + 255) / 256;
    const int NB = (NNODES + 255) / 256;
    const int WARP_N = (NNODES * 32 + 255) / 256;
    const int PB  = (NNODES * DPAD + 255) / 256;
    const int ELB = (NCF + 255) / 256;

    const uint32_t O_EMB = 0, O_W1 = 8192, O_W2 = 16384, O_MU = 24576,
                   O_GAT = 40960, O_DEC = 57344;

    // Our launch #4 = mm_gemm (harness prepends 2 launches; ncu -s 5 profiles it)
    packall_kernel<<<(73728 + 255) / 256, 256>>>(W_emb, W1, W2, W_mu, W_var, W_gat, W_dec);
    pad_nf_kernel<<<PB, 256>>>(nf);
    init_kernel<<<NB, 256>>>(eidx);
    mm_gemm<<<grid1, 256>>>(NF, DPAD, 4, NNODES, O_EMB, b_emb, nullptr, T, CF, 0,
                            nullptr, nullptr, nullptr, 1, nullptr, nullptr);
    // CSR build
    hist_kernel<<<EB, 256>>>(eidx);
    scan1_kernel<<<20, 1024>>>();
    scan3_kernel<<<20, 1024>>>();
    scatter_kernel<<<EB, 256>>>(eidx);
    bn_fin_kernel<<<1, 128>>>(g_embp, be_emb);

    // GIN layer 0 (agg applies emb-BN affine+relu to gathered rows of T)
    gin_agg_kernel<<<WARP_N, 256>>>(T, CS, CB);
    mm_gemm<<<grid1, 256>>>(Hb, CF, 4, NNODES, O_W1, b1, nullptr, T, CF, 0,
                            nullptr, nullptr, nullptr, 1, nullptr, nullptr);
    bn_fin_kernel<<<1, 128>>>(g1, be1);
    mm_gemm<<<grid1, 256>>>(T, CF, 4, NNODES, O_W2, b2, nullptr, X, CF, 0,
                            nullptr, CS, CB, 0, nullptr, nullptr);

    // GIN layer 1 (raw x)
    gin_agg_kernel<<<WARP_N, 256>>>(X, nullptr, nullptr);
    mm_gemm<<<grid1, 256>>>(Hb, CF, 4, NNODES, O_W1, b1, nullptr, T, CF, 0,
                            nullptr, nullptr, nullptr, 1, nullptr, nullptr);
    bn_fin_kernel<<<1, 128>>>(g1, be1);
    mm_gemm<<<grid1, 256>>>(T, CF, 4, NNODES, O_W2, b2, nullptr, X, CF, 0,
                            nullptr, CS, CB, 0, nullptr, nullptr);

    // VAE heads merged: nb=0 -> mu (out+2NCF), nb=1 -> logvar (out+3NCF)
    mm_gemm<<<grid2, 256>>>(X, CF, 4, NNODES, O_MU, b_mu, b_var,
                            out + 2 * NCF, CF, NCF,
                            nullptr, nullptr, nullptr, 0, nullptr, nullptr);
    z_kernel<<<ELB, 256>>>(eps, out);

    // GAT decoder x2 (shared weights); hh stored fp16
    for (int l = 0; l < 2; l++) {
        const float* zcur = (l == 0) ? out : ZOUT;
        float* zdst       = (l == 0) ? ZOUT : out + NCF;
        mm_gemm<<<grid2, 256>>>(zcur, CF, 4, NNODES, O_GAT, nullptr, nullptr,
                                nullptr, 0, 0, (__half2*)HHp,
                                nullptr, nullptr, 0, att_s, att_d);
        gat_agg_kernel<<<WARP_N, 256>>>(b_gat);
        mm_gemm<<<grid1, 256>>>(AGG, 256, 8, NNODES, O_DEC, b_dec, nullptr, zdst, CF, 0,
                                nullptr, nullptr, nullptr, 0, nullptr, nullptr);
    }
    (void)in_sizes; (void)n_in; (void)out_size;
}

// round 12
// speedup vs baseline: 1.2593x; 1.1040x over previous
#include <cuda_runtime.h>
#include <cuda_bf16.h>
#include <cuda_fp16.h>
#include <cstdint>

#define NNODES 20000
#define NEDGES 640000
#define DINF   92
#define DPAD   128
#define CF     128
#define NCF    (NNODES*CF)

// ---------------- scratch (device globals; no allocation) ----------------
__device__ __align__(16) float g_X[NCF];
__device__ __align__(16) float g_T[NCF];
__device__ __align__(16) float g_Hb[NCF];
__device__ __align__(16) float g_HHb[NNODES*128];   // half2: [n][128 pairs] = 256 ch
__device__ __align__(16) float g_AGG[NNODES*256];
__device__ __align__(16) float g_ZOUT[NCF];
__device__ __align__(16) float g_NF[NNODES*DPAD];
__device__ __align__(16) uint32_t g_BHI[98304];
__device__ __align__(16) uint32_t g_BLO[98304];
__device__ __align__(16) float g_AS[NNODES*2];
__device__ __align__(16) float g_AD[NNODES*2];
__device__ __align__(16) float g_S1[CF];
__device__ __align__(16) float g_S2[CF];
__device__ __align__(16) float g_cs[CF];
__device__ __align__(16) float g_cb[CF];
__device__ int   g_cnt[NNODES];
__device__ int   g_rowptr[NNODES+1];
__device__ int   g_cursor[NNODES];
__device__ int   g_csrc[NEDGES];
__device__ int   g_bsum[32];
__device__ int   g_is64;

// ---------------- bf16 hi/lo split + pack ----------------
__device__ __forceinline__ void split_pack(float e0, float e1,
                                           uint32_t& hp, uint32_t& lp) {
    unsigned short h0 = __bfloat16_as_ushort(__float2bfloat16_rn(e0));
    unsigned short h1 = __bfloat16_as_ushort(__float2bfloat16_rn(e1));
    float f0 = __uint_as_float((uint32_t)h0 << 16);
    float f1 = __uint_as_float((uint32_t)h1 << 16);
    unsigned short l0 = __bfloat16_as_ushort(__float2bfloat16_rn(e0 - f0));
    unsigned short l1 = __bfloat16_as_ushort(__float2bfloat16_rn(e1 - f1));
    hp = (uint32_t)h0 | ((uint32_t)h1 << 16);
    lp = (uint32_t)l0 | ((uint32_t)l1 << 16);
}

__device__ __forceinline__ void mma16816(float& d0, float& d1, float& d2, float& d3,
                                         uint32_t a0, uint32_t a1, uint32_t a2, uint32_t a3,
                                         uint32_t b0, uint32_t b1) {
    asm volatile(
        "mma.sync.aligned.m16n8k16.row.col.f32.bf16.bf16.f32 "
        "{%0,%1,%2,%3}, {%4,%5,%6,%7}, {%8,%9}, {%0,%1,%2,%3};"
        : "+f"(d0), "+f"(d1), "+f"(d2), "+f"(d3)
        : "r"(a0), "r"(a1), "r"(a2), "r"(a3), "r"(b0), "r"(b1));
}

__device__ __forceinline__ int edge_src(const void* p, int e) {
    return g_is64 ? (int)((const long long*)p)[e] : ((const int*)p)[e];
}
__device__ __forceinline__ int edge_dst(const void* p, int e) {
    return g_is64 ? (int)((const long long*)p)[NEDGES + e] : ((const int*)p)[NEDGES + e];
}

// ---------------- init: zero counters + stats, detect edge dtype ----------------
__global__ void init_kernel(const void* idx) {
    int i = blockIdx.x * blockDim.x + threadIdx.x;
    if (i < NNODES) g_cnt[i] = 0;
    if (i < CF) { g_S1[i] = 0.f; g_S2[i] = 0.f; }
    if (blockIdx.x == gridDim.x - 1) {
        const int* w = (const int*)idx;
        __shared__ int nz;
        if (threadIdx.x == 0) nz = 0;
        __syncthreads();
        for (int t = threadIdx.x; t < 4096; t += blockDim.x) {
            long long pos = 2LL * t * (NEDGES / 4096) + 1;
            if (pos < 2LL * NEDGES && w[pos] != 0) atomicOr(&nz, 1);
        }
        __syncthreads();
        if (threadIdx.x == 0) g_is64 = (nz == 0) ? 1 : 0;
    }
}

// ---------------- CSR build ----------------
__global__ void hist_kernel(const void* eidx) {
    int e = blockIdx.x * blockDim.x + threadIdx.x;
    if (e < NEDGES) atomicAdd(&g_cnt[edge_dst(eidx, e)], 1);
}
__global__ void scan1_kernel() {
    __shared__ int ws[32];
    int b = blockIdx.x, tid = threadIdx.x, lane = tid & 31, wid = tid >> 5;
    int i = b * 1024 + tid;
    int v = (i < NNODES) ? g_cnt[i] : 0;
    int x = v;
    #pragma unroll
    for (int o = 1; o < 32; o <<= 1) {
        int y = __shfl_up_sync(0xffffffffu, x, o);
        if (lane >= o) x += y;
    }
    if (lane == 31) ws[wid] = x;
    __syncthreads();
    if (wid == 0) {
        int s = ws[lane];
        #pragma unroll
        for (int o = 1; o < 32; o <<= 1) {
            int y = __shfl_up_sync(0xffffffffu, s, o);
            if (lane >= o) s += y;
        }
        ws[lane] = s;
    }
    __syncthreads();
    int incl = x + (wid > 0 ? ws[wid - 1] : 0);
    if (i < NNODES) g_rowptr[i] = incl - v;
    if (tid == 1023) g_bsum[b] = incl;
}
__global__ void scan3_kernel() {
    int b = blockIdx.x;
    int off = 0;
    #pragma unroll
    for (int j = 0; j < 20; j++) off += (j < b) ? g_bsum[j] : 0;
    int i = b * 1024 + threadIdx.x;
    if (i < NNODES) {
        int r = g_rowptr[i] + off;
        g_rowptr[i] = r;
        g_cursor[i] = r;
    }
    if (b == 0 && threadIdx.x == 0) {
        int t = 0;
        #pragma unroll
        for (int j = 0; j < 20; j++) t += g_bsum[j];
        g_rowptr[NNODES] = t;
    }
}
__global__ void scatter_kernel(const void* eidx) {
    int e = blockIdx.x * blockDim.x + threadIdx.x;
    if (e < NEDGES) {
        int d = edge_dst(eidx, e);
        int s = edge_src(eidx, e);
        int p = atomicAdd(&g_cursor[d], 1);
        g_csrc[p] = s;
    }
}

// ---------------- pad node features 92 -> 128 ----------------
__global__ void pad_nf_kernel(const float* __restrict__ nf) {
    int i = blockIdx.x * blockDim.x + threadIdx.x;
    if (i < NNODES * DPAD) {
        int n = i >> 7, c = i & 127;
        g_NF[i] = (c < DINF) ? nf[n * DINF + c] : 0.f;
    }
}

// ---------------- pack ALL weights in one launch ----------------
__global__ void packall_kernel(const float* __restrict__ We, const float* __restrict__ W1,
                               const float* __restrict__ W2, const float* __restrict__ Wm,
                               const float* __restrict__ Wv, const float* __restrict__ Wg,
                               const float* __restrict__ Wd) {
    int idx = blockIdx.x * blockDim.x + threadIdx.x;
    const float* W; int Kreal, Kpad, N; uint32_t base; int local;
    if      (idx <  8192) { W = We; Kreal = DINF; Kpad = 128; N = 128; base = 0;     local = idx; }
    else if (idx < 16384) { W = W1; Kreal = 128;  Kpad = 128; N = 128; base = 8192;  local = idx - 8192; }
    else if (idx < 24576) { W = W2; Kreal = 128;  Kpad = 128; N = 128; base = 16384; local = idx - 16384; }
    else if (idx < 32768) { W = Wm; Kreal = 128;  Kpad = 128; N = 128; base = 24576; local = idx - 24576; }
    else if (idx < 40960) { W = Wv; Kreal = 128;  Kpad = 128; N = 128; base = 32768; local = idx - 32768; }
    else if (idx < 57344) { W = Wg; Kreal = 128;  Kpad = 128; N = 256; base = 40960; local = idx - 40960; }
    else if (idx < 73728) { W = Wd; Kreal = 256;  Kpad = 256; N = 128; base = 57344; local = idx - 57344; }
    else return;
    int pairs = Kpad >> 1;
    int n = local / pairs, kp = local - n * pairs;
    int nb = n >> 7, nr = n & 127;
    int k0 = 2 * kp;
    float v0 = (k0     < Kreal) ? W[k0 * N + n]       : 0.f;
    float v1 = (k0 + 1 < Kreal) ? W[(k0 + 1) * N + n] : 0.f;
    uint32_t hp, lp;
    split_pack(v0, v1, hp, lp);
    uint32_t off = base + (uint32_t)nb * 128u * pairs + (uint32_t)nr * pairs + kp;
    g_BHI[off] = hp;
    g_BLO[off] = lp;
}

// ================= bf16 3-product mma.sync GEMM — 64x128 tile =================
// 8 warps, warp grid 2x4, warp tile 32x32. Grid.x = ceil(M/64), grid.y = nb.
// fp32 out: Out + nb*nbstride + row*ldo + cc. fp16 out (OutHf set): packed half2
// at [row][nb*64 + cc/2]. bias nb=0; bias2 nb=1.
__global__ void __launch_bounds__(256, 3)
mm_gemm(const float* __restrict__ A, int lda, int Kc, int M,
        uint32_t bbase,
        const float* __restrict__ bias, const float* __restrict__ bias2,
        float* __restrict__ Out, int ldo, int nbstride,
        __half2* __restrict__ OutHf,
        const float* __restrict__ affs, const float* __restrict__ affb,
        int do_stats,
        const float* __restrict__ atts, const float* __restrict__ attd)
{
    __shared__ uint32_t AHI[64 * 20], ALO[64 * 20];
    __shared__ uint32_t BHI[128 * 20], BLO[128 * 20];
    __shared__ float    RED1[128], RED2[128];

    const int tid = threadIdx.x, wid = tid >> 5, lane = tid & 31;
    const int g = lane >> 2, tc = lane & 3;
    const int wm = wid >> 2, wn = wid & 3;          // 2 x 4 warp grid
    const int r0 = blockIdx.x * 64;
    const int nb = blockIdx.y;
    const int pairsK = Kc * 16;
    const uint32_t bimg = bbase + (uint32_t)nb * 128u * pairsK;

    float acc[2][4][4];
    #pragma unroll
    for (int mt = 0; mt < 2; mt++)
        #pragma unroll
        for (int nt = 0; nt < 4; nt++)
            #pragma unroll
            for (int q = 0; q < 4; q++) acc[mt][nt][q] = 0.f;

    for (int c = 0; c < Kc; c++) {
        __syncthreads();
        // ---- stage A: 64 rows x 16 pairs (4 x 256)
        #pragma unroll
        for (int i = 0; i < 4; i++) {
            int idx = i * 256 + tid;
            int row = idx >> 4, p = idx & 15;
            int grow = r0 + row;
            float2 v = make_float2(0.f, 0.f);
            if (grow < M) {
                v = *(const float2*)&A[(size_t)grow * lda + c * 32 + p * 2];
                if (affs) {
                    int k = c * 32 + p * 2;
                    v.x = fmaxf(affs[k    ] * v.x + affb[k    ], 0.f);
                    v.y = fmaxf(affs[k + 1] * v.y + affb[k + 1], 0.f);
                }
            }
            uint32_t hp, lp;
            split_pack(v.x, v.y, hp, lp);
            AHI[row * 20 + p] = hp;
            ALO[row * 20 + p] = lp;
        }
        // ---- stage B: 128 n-rows x 16 pairs (8 x 256)
        #pragma unroll
        for (int i = 0; i < 8; i++) {
            int idx = i * 256 + tid;
            int n = idx >> 4, p = idx & 15;
            uint32_t src = bimg + (uint32_t)n * pairsK + c * 16 + p;
            BHI[n * 20 + p] = g_BHI[src];
            BLO[n * 20 + p] = g_BLO[src];
        }
        __syncthreads();

        #pragma unroll
        for (int prod = 0; prod < 3; prod++) {
            const uint32_t* Ab = (prod == 2) ? ALO : AHI;
            const uint32_t* Bb = (prod == 1) ? BLO : BHI;
            #pragma unroll
            for (int ks = 0; ks < 2; ks++) {
                uint32_t af[2][4], bf[4][2];
                #pragma unroll
                for (int mt = 0; mt < 2; mt++) {
                    int rbase = (wm * 32 + mt * 16 + g) * 20 + ks * 8 + tc;
                    af[mt][0] = Ab[rbase];
                    af[mt][1] = Ab[rbase + 8 * 20];
                    af[mt][2] = Ab[rbase + 4];
                    af[mt][3] = Ab[rbase + 8 * 20 + 4];
                }
                #pragma unroll
                for (int nt = 0; nt < 4; nt++) {
                    int nbase = (wn * 32 + nt * 8 + g) * 20 + ks * 8 + tc;
                    bf[nt][0] = Bb[nbase];
                    bf[nt][1] = Bb[nbase + 4];
                }
                #pragma unroll
                for (int mt = 0; mt < 2; mt++)
                    #pragma unroll
                    for (int nt = 0; nt < 4; nt++)
                        mma16816(acc[mt][nt][0], acc[mt][nt][1],
                                 acc[mt][nt][2], acc[mt][nt][3],
                                 af[mt][0], af[mt][1], af[mt][2], af[mt][3],
                                 bf[nt][0], bf[nt][1]);
            }
        }
    }

    // ---- epilogue
    const float* bsel = (nb == 1 && bias2) ? bias2 : bias;
    float bc[4][2];
    #pragma unroll
    for (int nt = 0; nt < 4; nt++) {
        int cc = wn * 32 + nt * 8 + tc * 2;
        bc[nt][0] = bsel ? bsel[cc]     : 0.f;
        bc[nt][1] = bsel ? bsel[cc + 1] : 0.f;
    }

    if (OutHf) {
        #pragma unroll
        for (int mt = 0; mt < 2; mt++) {
            int row0 = r0 + wm * 32 + mt * 16 + g;
            int row1 = row0 + 8;
            #pragma unroll
            for (int nt = 0; nt < 4; nt++) {
                int pidx = nb * 64 + (wn * 32 + nt * 8 + tc * 2) / 2;
                if (row0 < M)
                    OutHf[(size_t)row0 * 128 + pidx] =
                        __floats2half2_rn(acc[mt][nt][0], acc[mt][nt][1]);
                if (row1 < M)
                    OutHf[(size_t)row1 * 128 + pidx] =
                        __floats2half2_rn(acc[mt][nt][2], acc[mt][nt][3]);
            }
        }
    } else {
        float* outp = Out + (size_t)nb * nbstride;
        #pragma unroll
        for (int mt = 0; mt < 2; mt++) {
            int row0 = r0 + wm * 32 + mt * 16 + g;
            int row1 = row0 + 8;
            #pragma unroll
            for (int nt = 0; nt < 4; nt++) {
                int cc = wn * 32 + nt * 8 + tc * 2;
                if (row0 < M) {
                    float2 o = make_float2(acc[mt][nt][0] + bc[nt][0],
                                           acc[mt][nt][1] + bc[nt][1]);
                    *(float2*)&outp[(size_t)row0 * ldo + cc] = o;
                }
                if (row1 < M) {
                    float2 o = make_float2(acc[mt][nt][2] + bc[nt][0],
                                           acc[mt][nt][3] + bc[nt][1]);
                    *(float2*)&outp[(size_t)row1 * ldo + cc] = o;
                }
            }
        }
    }

    if (do_stats) {
        if (tid < CF) { RED1[tid] = 0.f; RED2[tid] = 0.f; }
        __syncthreads();
        #pragma unroll
        for (int nt = 0; nt < 4; nt++) {
            int ccl = wn * 32 + nt * 8 + tc * 2;
            float s0 = 0.f, q0 = 0.f, s1 = 0.f, q1 = 0.f;
            #pragma unroll
            for (int mt = 0; mt < 2; mt++) {
                int row0 = r0 + wm * 32 + mt * 16 + g;
                if (row0 < M) {
                    float v0 = acc[mt][nt][0] + bc[nt][0];
                    float v1 = acc[mt][nt][1] + bc[nt][1];
                    s0 += v0; q0 += v0 * v0; s1 += v1; q1 += v1 * v1;
                }
                if (row0 + 8 < M) {
                    float v0 = acc[mt][nt][2] + bc[nt][0];
                    float v1 = acc[mt][nt][3] + bc[nt][1];
                    s0 += v0; q0 += v0 * v0; s1 += v1; q1 += v1 * v1;
                }
            }
            atomicAdd(&RED1[ccl], s0); atomicAdd(&RED2[ccl], q0);
            atomicAdd(&RED1[ccl + 1], s1); atomicAdd(&RED2[ccl + 1], q1);
        }
        __syncthreads();
        if (tid < CF) { atomicAdd(&g_S1[tid], RED1[tid]); atomicAdd(&g_S2[tid], RED2[tid]); }
    }

    if (atts) {   // tile covers rows r0..r0+63
        if (tid < 64) { RED1[tid] = 0.f; RED2[tid] = 0.f; }
        __syncthreads();
        float avs[4][2], avd[4][2];
        #pragma unroll
        for (int nt = 0; nt < 4; nt++) {
            int cc = wn * 32 + nt * 8 + tc * 2;
            avs[nt][0] = atts[nb * CF + cc]; avs[nt][1] = atts[nb * CF + cc + 1];
            avd[nt][0] = attd[nb * CF + cc]; avd[nt][1] = attd[nb * CF + cc + 1];
        }
        #pragma unroll
        for (int mt = 0; mt < 2; mt++) {
            float ss0 = 0.f, sd0 = 0.f, ss1 = 0.f, sd1 = 0.f;
            #pragma unroll
            for (int nt = 0; nt < 4; nt++) {
                ss0 += acc[mt][nt][0] * avs[nt][0] + acc[mt][nt][1] * avs[nt][1];
                sd0 += acc[mt][nt][0] * avd[nt][0] + acc[mt][nt][1] * avd[nt][1];
                ss1 += acc[mt][nt][2] * avs[nt][0] + acc[mt][nt][3] * avs[nt][1];
                sd1 += acc[mt][nt][2] * avd[nt][0] + acc[mt][nt][3] * avd[nt][1];
            }
            int rl = wm * 32 + mt * 16 + g;
            atomicAdd(&RED1[rl], ss0);     atomicAdd(&RED2[rl], sd0);
            atomicAdd(&RED1[rl + 8], ss1); atomicAdd(&RED2[rl + 8], sd1);
        }
        __syncthreads();
        if (tid < 64 && r0 + tid < M) {
            g_AS[(r0 + tid) * 2 + nb] = RED1[tid];
            g_AD[(r0 + tid) * 2 + nb] = RED2[tid];
        }
    }
}

// ---------------- z = eps*exp(0.5*logvar)+mu ----------------
__global__ void z_kernel(const float* __restrict__ eps, float* __restrict__ out) {
    int i = blockIdx.x * blockDim.x + threadIdx.x;
    if (i < NCF) {
        float mu = out[2 * NCF + i];
        float lv = out[3 * NCF + i];
        out[i] = eps[i] * expf(0.5f * lv) + mu;
    }
}

// ---------------- BN finalize (self-resetting stats) ----------------
__global__ void bn_fin_kernel(const float* __restrict__ gam, const float* __restrict__ bet) {
    int c = threadIdx.x;
    if (c < CF) {
        float s1 = g_S1[c], s2 = g_S2[c];
        float mu  = s1 / (float)NNODES;
        float var = s2 / (float)NNODES - mu * mu;
        float a   = gam[c] * rsqrtf(var + 1e-5f);
        g_cs[c] = a;
        g_cb[c] = bet[c] - mu * a;
        g_S1[c] = 0.f;
        g_S2[c] = 0.f;
    }
}

// ---------------- GIN aggregation (optional fused affine+relu on gathered rows) ----
__global__ void gin_agg_kernel(const float* __restrict__ src,
                               const float* __restrict__ cs,
                               const float* __restrict__ cb) {
    int warp = (blockIdx.x * blockDim.x + threadIdx.x) >> 5;
    int lane = threadIdx.x & 31;
    if (warp >= NNODES) return;
    int n = warp;
    const bool aff = (cs != nullptr);
    float4 sc = make_float4(1.f, 1.f, 1.f, 1.f), bb = make_float4(0.f, 0.f, 0.f, 0.f);
    if (aff) {
        sc = *(const float4*)&cs[lane * 4];
        bb = *(const float4*)&cb[lane * 4];
    }
    float4 acc = *(const float4*)&src[n * CF + lane * 4];
    if (aff) {
        acc.x = fmaxf(sc.x * acc.x + bb.x, 0.f);
        acc.y = fmaxf(sc.y * acc.y + bb.y, 0.f);
        acc.z = fmaxf(sc.z * acc.z + bb.z, 0.f);
        acc.w = fmaxf(sc.w * acc.w + bb.w, 0.f);
    }
    int beg = g_rowptr[n], end = g_rowptr[n + 1];
    int i = beg;
    for (; i + 1 < end; i += 2) {
        int s0 = g_csrc[i], s1v = g_csrc[i + 1];
        float4 v0 = *(const float4*)&src[s0 * CF + lane * 4];
        float4 v1 = *(const float4*)&src[s1v * CF + lane * 4];
        if (aff) {
            v0.x = fmaxf(sc.x * v0.x + bb.x, 0.f); v0.y = fmaxf(sc.y * v0.y + bb.y, 0.f);
            v0.z = fmaxf(sc.z * v0.z + bb.z, 0.f); v0.w = fmaxf(sc.w * v0.w + bb.w, 0.f);
            v1.x = fmaxf(sc.x * v1.x + bb.x, 0.f); v1.y = fmaxf(sc.y * v1.y + bb.y, 0.f);
            v1.z = fmaxf(sc.z * v1.z + bb.z, 0.f); v1.w = fmaxf(sc.w * v1.w + bb.w, 0.f);
        }
        acc.x += v0.x + v1.x; acc.y += v0.y + v1.y;
        acc.z += v0.z + v1.z; acc.w += v0.w + v1.w;
    }
    if (i < end) {
        int s0 = g_csrc[i];
        float4 v0 = *(const float4*)&src[s0 * CF + lane * 4];
        if (aff) {
            v0.x = fmaxf(sc.x * v0.x + bb.x, 0.f); v0.y = fmaxf(sc.y * v0.y + bb.y, 0.f);
            v0.z = fmaxf(sc.z * v0.z + bb.z, 0.f); v0.w = fmaxf(sc.w * v0.w + bb.w, 0.f);
        }
        acc.x += v0.x; acc.y += v0.y; acc.z += v0.z; acc.w += v0.w;
    }
    *(float4*)&g_Hb[n * CF + lane * 4] = acc;
}

__device__ __forceinline__ float lrelu(float x) { return x > 0.f ? x : 0.2f * x; }

__device__ __forceinline__ float4 h2x2_to_f4(__half2 p0, __half2 p1) {
    float2 a = __half22float2(p0), b = __half22float2(p1);
    return make_float4(a.x, a.y, b.x, b.y);
}

// ---------------- GAT aggregation: ONE warp per node, BOTH heads (fp16 hh) -----
__global__ void gat_agg_kernel(const float* __restrict__ b_gat) {
    int warp = (blockIdx.x * blockDim.x + threadIdx.x) >> 5;
    int lane = threadIdx.x & 31;
    if (warp >= NNODES) return;
    int n = warp;
    const __half2* hh = (const __half2*)g_HHb;
    float2 ad  = *(const float2*)&g_AD[n * 2];
    float2 asn = *(const float2*)&g_AS[n * 2];
    float ls0 = lrelu(asn.x + ad.x);
    float ls1 = lrelu(asn.y + ad.y);
    int beg = g_rowptr[n], end = g_rowptr[n + 1];

    float m0 = ls0, m1 = ls1;
    for (int i = beg + lane; i < end; i += 32) {
        int s = g_csrc[i];
        float2 a = *(const float2*)&g_AS[s * 2];
        m0 = fmaxf(m0, lrelu(a.x + ad.x));
        m1 = fmaxf(m1, lrelu(a.y + ad.y));
    }
    #pragma unroll
    for (int o = 16; o >= 1; o >>= 1) {
        m0 = fmaxf(m0, __shfl_xor_sync(0xffffffffu, m0, o));
        m1 = fmaxf(m1, __shfl_xor_sync(0xffffffffu, m1, o));
    }

    float w0 = expf(ls0 - m0), w1 = expf(ls1 - m1);
    float s0 = w0, s1 = w1;
    const __half2* hn = &hh[(size_t)n * 128];
    float4 h0 = h2x2_to_f4(hn[lane * 2], hn[lane * 2 + 1]);
    float4 h1 = h2x2_to_f4(hn[64 + lane * 2], hn[64 + lane * 2 + 1]);
    float4 acc0 = make_float4(w0 * h0.x, w0 * h0.y, w0 * h0.z, w0 * h0.w);
    float4 acc1 = make_float4(w1 * h1.x, w1 * h1.y, w1 * h1.z, w1 * h1.w);
    int i = beg;
    for (; i + 1 < end; i += 2) {
        int sa = g_csrc[i], sb = g_csrc[i + 1];
        float2 aa = *(const float2*)&g_AS[sa * 2];
        float2 ab = *(const float2*)&g_AS[sb * 2];
        float ea0 = expf(lrelu(aa.x + ad.x) - m0), ea1 = expf(lrelu(aa.y + ad.y) - m1);
        float eb0 = expf(lrelu(ab.x + ad.x) - m0), eb1 = expf(lrelu(ab.y + ad.y) - m1);
        s0 += ea0 + eb0; s1 += ea1 + eb1;
        const __half2* ha = &hh[(size_t)sa * 128];
        const __half2* hb2 = &hh[(size_t)sb * 128];
        float4 va0 = h2x2_to_f4(ha[lane * 2], ha[lane * 2 + 1]);
        float4 va1 = h2x2_to_f4(ha[64 + lane * 2], ha[64 + lane * 2 + 1]);
        float4 vb0 = h2x2_to_f4(hb2[lane * 2], hb2[lane * 2 + 1]);
        float4 vb1 = h2x2_to_f4(hb2[64 + lane * 2], hb2[64 + lane * 2 + 1]);
        acc0.x += ea0 * va0.x + eb0 * vb0.x; acc0.y += ea0 * va0.y + eb0 * vb0.y;
        acc0.z += ea0 * va0.z + eb0 * vb0.z; acc0.w += ea0 * va0.w + eb0 * vb0.w;
        acc1.x += ea1 * va1.x + eb1 * vb1.x; acc1.y += ea1 * va1.y + eb1 * vb1.y;
        acc1.z += ea1 * va1.z + eb1 * vb1.z; acc1.w += ea1 * va1.w + eb1 * vb1.w;
    }
    if (i < end) {
        int sa = g_csrc[i];
        float2 aa = *(const float2*)&g_AS[sa * 2];
        float ea0 = expf(lrelu(aa.x + ad.x) - m0), ea1 = expf(lrelu(aa.y + ad.y) - m1);
        s0 += ea0; s1 += ea1;
        const __half2* ha = &hh[(size_t)sa * 128];
        float4 va0 = h2x2_to_f4(ha[lane * 2], ha[lane * 2 + 1]);
        float4 va1 = h2x2_to_f4(ha[64 + lane * 2], ha[64 + lane * 2 + 1]);
        acc0.x += ea0 * va0.x; acc0.y += ea0 * va0.y;
        acc0.z += ea0 * va0.z; acc0.w += ea0 * va0.w;
        acc1.x += ea1 * va1.x; acc1.y += ea1 * va1.y;
        acc1.z += ea1 * va1.z; acc1.w += ea1 * va1.w;
    }
    float i0 = 1.f / s0, i1 = 1.f / s1;
    float4 bg0 = *(const float4*)&b_gat[lane * 4];
    float4 bg1 = *(const float4*)&b_gat[128 + lane * 4];
    float4 o0 = make_float4(acc0.x * i0 + bg0.x, acc0.y * i0 + bg0.y,
                            acc0.z * i0 + bg0.z, acc0.w * i0 + bg0.w);
    float4 o1 = make_float4(acc1.x * i1 + bg1.x, acc1.y * i1 + bg1.y,
                            acc1.z * i1 + bg1.z, acc1.w * i1 + bg1.w);
    *(float4*)&g_AGG[n * 256 + lane * 4]       = o0;
    *(float4*)&g_AGG[n * 256 + 128 + lane * 4] = o1;
}

// ---------------- host orchestration ----------------
extern "C" void kernel_launch(void* const* d_in, const int* in_sizes, int n_in,
                              void* d_out, int out_size) {
    const float* nf     = (const float*)d_in[0];
    const void*  eidx   =               d_in[1];
    const float* eps    = (const float*)d_in[2];
    const float* W_emb  = (const float*)d_in[3];
    const float* b_emb  = (const float*)d_in[4];
    const float* g_embp = (const float*)d_in[5];
    const float* be_emb = (const float*)d_in[6];
    const float* W1     = (const float*)d_in[7];
    const float* b1     = (const float*)d_in[8];
    const float* g1     = (const float*)d_in[9];
    const float* be1    = (const float*)d_in[10];
    const float* W2     = (const float*)d_in[11];
    const float* b2     = (const float*)d_in[12];
    const float* W_mu   = (const float*)d_in[13];
    const float* b_mu   = (const float*)d_in[14];
    const float* W_var  = (const float*)d_in[15];
    const float* b_var  = (const float*)d_in[16];
    const float* W_gat  = (const float*)d_in[17];
    const float* att_s  = (const float*)d_in[18];
    const float* att_d  = (const float*)d_in[19];
    const float* b_gat  = (const float*)d_in[20];
    const float* W_dec  = (const float*)d_in[21];
    const float* b_dec  = (const float*)d_in[22];
    float* out = (float*)d_out;

    float *X, *T, *Hb, *HHp, *AGG, *ZOUT, *CS, *CB, *NF;
    cudaGetSymbolAddress((void**)&X,    g_X);
    cudaGetSymbolAddress((void**)&T,    g_T);
    cudaGetSymbolAddress((void**)&Hb,   g_Hb);
    cudaGetSymbolAddress((void**)&HHp,  g_HHb);
    cudaGetSymbolAddress((void**)&AGG,  g_AGG);
    cudaGetSymbolAddress((void**)&ZOUT, g_ZOUT);
    cudaGetSymbolAddress((void**)&CS,   g_cs);
    cudaGetSymbolAddress((void**)&CB,   g_cb);
    cudaGetSymbolAddress((void**)&NF,   g_NF);

    const int GX = (NNODES + 63) / 64;   // 313
    dim3 grid1(GX, 1), grid2(GX, 2);
    const int EB = (NEDGES + 255) / 256;
    const int NB = (NNODES + 255) / 256;
    const int WARP_N = (NNODES * 32 + 255) / 256;
    const int PB  = (NNODES * DPAD + 255) / 256;
    const int ELB = (NCF + 255) / 256;

    const uint32_t O_EMB = 0, O_W1 = 8192, O_W2 = 16384, O_MU = 24576,
                   O_GAT = 40960, O_DEC = 57344;

    // Our launch #4 = mm_gemm (harness prepends 2 launches; ncu -s 5 profiles it)
    packall_kernel<<<(73728 + 255) / 256, 256>>>(W_emb, W1, W2, W_mu, W_var, W_gat, W_dec);
    pad_nf_kernel<<<PB, 256>>>(nf);
    init_kernel<<<NB, 256>>>(eidx);
    mm_gemm<<<grid1, 256>>>(NF, DPAD, 4, NNODES, O_EMB, b_emb, nullptr, T, CF, 0,
                            nullptr, nullptr, nullptr, 1, nullptr, nullptr);
    // CSR build
    hist_kernel<<<EB, 256>>>(eidx);
    scan1_kernel<<<20, 1024>>>();
    scan3_kernel<<<20, 1024>>>();
    scatter_kernel<<<EB, 256>>>(eidx);
    bn_fin_kernel<<<1, 128>>>(g_embp, be_emb);

    // GIN layer 0 (agg applies emb-BN affine+relu to gathered rows of T)
    gin_agg_kernel<<<WARP_N, 256>>>(T, CS, CB);
    mm_gemm<<<grid1, 256>>>(Hb, CF, 4, NNODES, O_W1, b1, nullptr, T, CF, 0,
                            nullptr, nullptr, nullptr, 1, nullptr, nullptr);
    bn_fin_kernel<<<1, 128>>>(g1, be1);
    mm_gemm<<<grid1, 256>>>(T, CF, 4, NNODES, O_W2, b2, nullptr, X, CF, 0,
                            nullptr, CS, CB, 0, nullptr, nullptr);

    // GIN layer 1 (raw x)
    gin_agg_kernel<<<WARP_N, 256>>>(X, nullptr, nullptr);
    mm_gemm<<<grid1, 256>>>(Hb, CF, 4, NNODES, O_W1, b1, nullptr, T, CF, 0,
                            nullptr, nullptr, nullptr, 1, nullptr, nullptr);
    bn_fin_kernel<<<1, 128>>>(g1, be1);
    mm_gemm<<<grid1, 256>>>(T, CF, 4, NNODES, O_W2, b2, nullptr, X, CF, 0,
                            nullptr, CS, CB, 0, nullptr, nullptr);

    // VAE heads merged: nb=0 -> mu (out+2NCF), nb=1 -> logvar (out+3NCF)
    mm_gemm<<<grid2, 256>>>(X, CF, 4, NNODES, O_MU, b_mu, b_var,
                            out + 2 * NCF, CF, NCF,
                            nullptr, nullptr, nullptr, 0, nullptr, nullptr);
    z_kernel<<<ELB, 256>>>(eps, out);

    // GAT decoder x2 (shared weights); hh stored fp16
    for (int l = 0; l < 2; l++) {
        const float* zcur = (l == 0) ? out : ZOUT;
        float* zdst       = (l == 0) ? ZOUT : out + NCF;
        mm_gemm<<<grid2, 256>>>(zcur, CF, 4, NNODES, O_GAT, nullptr, nullptr,
                                nullptr, 0, 0, (__half2*)HHp,
                                nullptr, nullptr, 0, att_s, att_d);
        gat_agg_kernel<<<WARP_N, 256>>>(b_gat);
        mm_gemm<<<grid1, 256>>>(AGG, 256, 8, NNODES, O_DEC, b_dec, nullptr, zdst, CF, 0,
                                nullptr, nullptr, nullptr, 0, nullptr, nullptr);
    }
    (void)in_sizes; (void)n_in; (void)out_size;
}